// round 10
// baseline (speedup 1.0000x reference)
#include <cuda_runtime.h>
#include <cuda_fp16.h>
#include <cstdint>
#include <cstddef>

// Problem dims
#define DIMV   1024
#define HIDV   4096
#define SEQ    2048
#define NHEAD  16
#define HDIMV  64
#define NTOK   8192          // B * S
#define QKV_LD 3072          // fused QKV row stride

// GEMM tiling (fp16 mma m16n8k16): 128x128 tile, 32 K per stage
#define BM 128
#define BN 128
#define BKS16 32
#define TILE_H 2560          // 128 rows * 20 b32 (40 halves padded)
#define STAGE_H 5120
#define GEMM_SMEM_BYTES (3 * STAGE_H * 4)   // 61440

// attention smem (fp16 tiles)
#define AT_PADH 72                         // halves per row (64 + 8 pad)
#define AT_TILEH (64 * AT_PADH)            // halves per tile
#define ATTN_SMEM_B (5 * AT_TILEH * 2)     // K[2]+V[2]+P = 46080 B

// ---------------- static scratch ----------------
__device__ __half g_h  [(size_t)NTOK * DIMV];     // ln1(x) fp16
__device__ __half g_qkv[(size_t)NTOK * QKV_LD];   // fused Q|K|V fp16
__device__ float  g_o  [(size_t)NTOK * DIMV];
__device__ float  g_x2 [(size_t)NTOK * DIMV];
__device__ __half g_h2 [(size_t)NTOK * DIMV];
__device__ __half g_mid[(size_t)NTOK * HIDV];
__device__ __half g_wt [(size_t)QKV_LD * DIMV];
__device__ __half g_w1t[(size_t)HIDV * DIMV];
__device__ __half g_w2t[(size_t)DIMV * HIDV];
__device__ float  g_bqkv[QKV_LD];

// ---------------- helpers ----------------
__device__ __forceinline__ uint32_t smem_u32(const void* p) {
    uint32_t a;
    asm("{ .reg .u64 t; cvta.to.shared.u64 t, %1; cvt.u32.u64 %0, t; }" : "=r"(a) : "l"(p));
    return a;
}

__device__ __forceinline__ float gelu_exact(float x) {
    return 0.5f * x * (1.0f + erff(x * 0.70710678118654752f));
}

__device__ __forceinline__ void cp_async16(uint32_t dst, const void* src) {
    asm volatile("cp.async.cg.shared.global [%0], [%1], 16;" :: "r"(dst), "l"(src));
}
#define CP_COMMIT() asm volatile("cp.async.commit_group;" ::: "memory")
#define CP_WAIT1()  asm volatile("cp.async.wait_group 1;" ::: "memory")
#define CP_WAIT0()  asm volatile("cp.async.wait_group 0;" ::: "memory")

__device__ __forceinline__ void mma_f16(float* c, const uint32_t* a, const uint32_t* b) {
    asm volatile(
        "mma.sync.aligned.m16n8k16.row.col.f32.f16.f16.f32 "
        "{%0,%1,%2,%3}, {%4,%5,%6,%7}, {%8,%9}, {%0,%1,%2,%3};"
        : "+f"(c[0]), "+f"(c[1]), "+f"(c[2]), "+f"(c[3])
        : "r"(a[0]), "r"(a[1]), "r"(a[2]), "r"(a[3]), "r"(b[0]), "r"(b[1]));
}

// ---------------- weight transposes (fp16 output) ----------------
__global__ void transpose_kernel_h16(const float* __restrict__ src, __half* __restrict__ dst,
                                     int R, int C)
{
    __shared__ float t[32][33];
    int c0 = blockIdx.x * 32, r0 = blockIdx.y * 32;
    int tx = threadIdx.x, ty = threadIdx.y;
    #pragma unroll
    for (int i = 0; i < 32; i += 8)
        t[ty + i][tx] = src[(size_t)(r0 + ty + i) * C + c0 + tx];
    __syncthreads();
    #pragma unroll
    for (int i = 0; i < 32; i += 8)
        dst[(size_t)(c0 + ty + i) * R + r0 + tx] = __float2half_rn(t[tx][ty + i]);
}

__global__ void transpose_qkv_kernel(const float* __restrict__ Wq, const float* __restrict__ Wk,
                                     const float* __restrict__ Wv, __half* __restrict__ dst)
{
    __shared__ float t[32][33];
    int s = blockIdx.z, w = s >> 4, h = s & 15;
    const float* W = ((w == 0) ? Wq : (w == 1) ? Wk : Wv) + (size_t)h * DIMV * HDIMV;
    __half* D = dst + (size_t)(w * 1024 + h * 64) * DIMV;
    int c0 = blockIdx.x * 32, r0 = blockIdx.y * 32;
    int tx = threadIdx.x, ty = threadIdx.y;
    #pragma unroll
    for (int i = 0; i < 32; i += 8)
        t[ty + i][tx] = W[(size_t)(r0 + ty + i) * HDIMV + c0 + tx];
    __syncthreads();
    #pragma unroll
    for (int i = 0; i < 32; i += 8)
        D[(size_t)(c0 + ty + i) * DIMV + r0 + tx] = __float2half_rn(t[tx][ty + i]);
}

__global__ void pack_bias_kernel(const float* __restrict__ bq, const float* __restrict__ bk,
                                 const float* __restrict__ bv, float* __restrict__ dst)
{
    int i = blockIdx.x * 256 + threadIdx.x;
    float v = (i < 1024) ? bq[i] : (i < 2048) ? bk[i - 1024] : bv[i - 2048];
    dst[i] = v;
}

// ---------------- LayerNorm (fp16 output) ----------------
__global__ void ln_kernel(const float* __restrict__ x, const float* __restrict__ g,
                          const float* __restrict__ b, __half* __restrict__ y)
{
    __shared__ float s_a[8], s_b[8];
    __shared__ float s_mu, s_rs;
    size_t row = blockIdx.x;
    int tid = threadIdx.x;
    float4 v = ((const float4*)(x + row * DIMV))[tid];
    float sum = v.x + v.y + v.z + v.w;
    float sq  = v.x*v.x + v.y*v.y + v.z*v.z + v.w*v.w;
    #pragma unroll
    for (int o = 16; o; o >>= 1) {
        sum += __shfl_xor_sync(0xffffffffu, sum, o);
        sq  += __shfl_xor_sync(0xffffffffu, sq,  o);
    }
    if ((tid & 31) == 0) { s_a[tid >> 5] = sum; s_b[tid >> 5] = sq; }
    __syncthreads();
    if (tid == 0) {
        float ts = 0.f, tq = 0.f;
        #pragma unroll
        for (int i = 0; i < 8; i++) { ts += s_a[i]; tq += s_b[i]; }
        float mu  = ts * (1.0f / DIMV);
        float var = tq * (1.0f / DIMV) - mu * mu;
        s_mu = mu; s_rs = rsqrtf(var + 1e-5f);
    }
    __syncthreads();
    float mu = s_mu, rs = s_rs;
    float4 gv = ((const float4*)g)[tid];
    float4 bv = ((const float4*)b)[tid];
    __half2 h0, h1;
    h0.x = __float2half_rn((v.x - mu) * rs * gv.x + bv.x);
    h0.y = __float2half_rn((v.y - mu) * rs * gv.y + bv.y);
    h1.x = __float2half_rn((v.z - mu) * rs * gv.z + bv.z);
    h1.y = __float2half_rn((v.w - mu) * rs * gv.w + bv.w);
    ((__half2*)(y + row * DIMV))[tid * 2 + 0] = h0;
    ((__half2*)(y + row * DIMV))[tid * 2 + 1] = h1;
}

// ---------------- residual add + LN(ln2) + LN(fcln), h2 out fp16 ----------------
__global__ void add_dln_kernel(const float* __restrict__ x, const float* __restrict__ oatt,
                               const float* __restrict__ g2, const float* __restrict__ b2,
                               const float* __restrict__ gf, const float* __restrict__ bf,
                               float* __restrict__ x2, __half* __restrict__ h2)
{
    __shared__ float s_a[8], s_b[8];
    __shared__ float s_mu, s_rs;
    size_t row = blockIdx.x;
    int tid = threadIdx.x;
    float4 v  = ((const float4*)(x    + row * DIMV))[tid];
    float4 ov = ((const float4*)(oatt + row * DIMV))[tid];
    v.x += ov.x; v.y += ov.y; v.z += ov.z; v.w += ov.w;
    ((float4*)(x2 + row * DIMV))[tid] = v;

    float sum = v.x + v.y + v.z + v.w;
    float sq  = v.x*v.x + v.y*v.y + v.z*v.z + v.w*v.w;
    #pragma unroll
    for (int o = 16; o; o >>= 1) {
        sum += __shfl_xor_sync(0xffffffffu, sum, o);
        sq  += __shfl_xor_sync(0xffffffffu, sq,  o);
    }
    if ((tid & 31) == 0) { s_a[tid >> 5] = sum; s_b[tid >> 5] = sq; }
    __syncthreads();
    if (tid == 0) {
        float ts = 0.f, tq = 0.f;
        #pragma unroll
        for (int i = 0; i < 8; i++) { ts += s_a[i]; tq += s_b[i]; }
        float mu  = ts * (1.0f / DIMV);
        float var = tq * (1.0f / DIMV) - mu * mu;
        s_mu = mu; s_rs = rsqrtf(var + 1e-5f);
    }
    __syncthreads();
    float mu1 = s_mu, rs1 = s_rs;
    float4 g2v = ((const float4*)g2)[tid];
    float4 b2v = ((const float4*)b2)[tid];
    float4 t;
    t.x = (v.x - mu1) * rs1 * g2v.x + b2v.x;
    t.y = (v.y - mu1) * rs1 * g2v.y + b2v.y;
    t.z = (v.z - mu1) * rs1 * g2v.z + b2v.z;
    t.w = (v.w - mu1) * rs1 * g2v.w + b2v.w;

    float sum2 = t.x + t.y + t.z + t.w;
    float sq2  = t.x*t.x + t.y*t.y + t.z*t.z + t.w*t.w;
    #pragma unroll
    for (int o = 16; o; o >>= 1) {
        sum2 += __shfl_xor_sync(0xffffffffu, sum2, o);
        sq2  += __shfl_xor_sync(0xffffffffu, sq2,  o);
    }
    if ((tid & 31) == 0) { s_a[tid >> 5] = sum2; s_b[tid >> 5] = sq2; }
    __syncthreads();
    if (tid == 0) {
        float ts = 0.f, tq = 0.f;
        #pragma unroll
        for (int i = 0; i < 8; i++) { ts += s_a[i]; tq += s_b[i]; }
        float mu  = ts * (1.0f / DIMV);
        float var = tq * (1.0f / DIMV) - mu * mu;
        s_mu = mu; s_rs = rsqrtf(var + 1e-5f);
    }
    __syncthreads();
    float mu2 = s_mu, rs2 = s_rs;
    float4 gfv = ((const float4*)gf)[tid];
    float4 bfv = ((const float4*)bf)[tid];
    __half2 h0, h1;
    h0.x = __float2half_rn((t.x - mu2) * rs2 * gfv.x + bfv.x);
    h0.y = __float2half_rn((t.y - mu2) * rs2 * gfv.y + bfv.y);
    h1.x = __float2half_rn((t.z - mu2) * rs2 * gfv.z + bfv.z);
    h1.y = __float2half_rn((t.w - mu2) * rs2 * gfv.w + bfv.w);
    ((__half2*)(h2 + row * DIMV))[tid * 2 + 0] = h0;
    ((__half2*)(h2 + row * DIMV))[tid * 2 + 1] = h1;
}

// ---------------- fp16 GEMM: C = act(A @ Bt^T + bias) (+res) ----------------
template<int ACT, int RES, int OUT16>
__global__ void __launch_bounds__(256) gemm_f16(
    const __half* __restrict__ A, const __half* __restrict__ Bt,
    const float* __restrict__ bias, const float* __restrict__ resid,
    void* __restrict__ Cout, int N, int K)
{
    extern __shared__ float sm[];
    uint32_t* smu = (uint32_t*)sm;
    const int tid  = threadIdx.x;
    const int lane = tid & 31;
    const int warp = tid >> 5;
    const int wm = warp >> 2;
    const int wn = warp & 3;
    const int m0 = blockIdx.y * BM;
    const int n0 = blockIdx.x * BN;
    const int KT = K / BKS16;

    const int lrow = tid >> 2;
    const int lk8  = (tid & 3) * 8;
    const int lk4  = (tid & 3) * 4;

    const __half* Asrc0 = A  + (size_t)(m0 + lrow)      * K + lk8;
    const __half* Asrc1 = A  + (size_t)(m0 + lrow + 64) * K + lk8;
    const __half* Bsrc0 = Bt + (size_t)(n0 + lrow)      * K + lk8;
    const __half* Bsrc1 = Bt + (size_t)(n0 + lrow + 64) * K + lk8;

    const uint32_t smb = smem_u32(sm);
    const uint32_t dA0 = smb + ((lrow)      * 20 + lk4) * 4;
    const uint32_t dA1 = smb + ((lrow + 64) * 20 + lk4) * 4;
    const uint32_t dB0 = dA0 + TILE_H * 4;
    const uint32_t dB1 = dA1 + TILE_H * 4;

    #pragma unroll
    for (int s = 0; s < 2; s++) {
        uint32_t off = s * STAGE_H * 4;
        int k0 = s * BKS16;
        cp_async16(dA0 + off, Asrc0 + k0);
        cp_async16(dA1 + off, Asrc1 + k0);
        cp_async16(dB0 + off, Bsrc0 + k0);
        cp_async16(dB1 + off, Bsrc1 + k0);
        CP_COMMIT();
    }

    float acc[4][4][4] = {};
    const int gr = lane >> 2;
    const int tg = lane & 3;

    for (int kt = 0; kt < KT; kt++) {
        CP_WAIT1();
        __syncthreads();
        const uint32_t* As = smu + (kt % 3) * STAGE_H;
        const uint32_t* Bs = As + TILE_H;

        #pragma unroll
        for (int kc = 0; kc < 2; kc++) {
            uint32_t af[4][4], bf[4][2];
            #pragma unroll
            for (int mb = 0; mb < 4; mb++) {
                int r = wm * 64 + mb * 16 + gr;
                af[mb][0] = As[(r)     * 20 + kc * 8 + tg];
                af[mb][1] = As[(r + 8) * 20 + kc * 8 + tg];
                af[mb][2] = As[(r)     * 20 + kc * 8 + 4 + tg];
                af[mb][3] = As[(r + 8) * 20 + kc * 8 + 4 + tg];
            }
            #pragma unroll
            for (int nb = 0; nb < 4; nb++) {
                int c = wn * 32 + nb * 8 + gr;
                bf[nb][0] = Bs[c * 20 + kc * 8 + tg];
                bf[nb][1] = Bs[c * 20 + kc * 8 + 4 + tg];
            }
            #pragma unroll
            for (int mb = 0; mb < 4; mb++)
                #pragma unroll
                for (int nb = 0; nb < 4; nb++)
                    mma_f16(acc[mb][nb], af[mb], bf[nb]);
        }

        if (kt + 2 < KT) {
            uint32_t off = ((kt + 2) % 3) * STAGE_H * 4;
            int k0 = (kt + 2) * BKS16;
            cp_async16(dA0 + off, Asrc0 + k0);
            cp_async16(dA1 + off, Asrc1 + k0);
            cp_async16(dB0 + off, Bsrc0 + k0);
            cp_async16(dB1 + off, Bsrc1 + k0);
        }
        CP_COMMIT();
        __syncthreads();
    }

    #pragma unroll
    for (int mb = 0; mb < 4; mb++) {
        int rlo = m0 + wm * 64 + mb * 16 + gr;
        #pragma unroll
        for (int nb = 0; nb < 4; nb++) {
            int col = n0 + wn * 32 + nb * 8 + tg * 2;
            float2 bi = *(const float2*)(bias + col);
            #pragma unroll
            for (int half_i = 0; half_i < 2; half_i++) {
                int row = rlo + half_i * 8;
                float v0 = acc[mb][nb][half_i * 2 + 0] + bi.x;
                float v1 = acc[mb][nb][half_i * 2 + 1] + bi.y;
                if (ACT) { v0 = gelu_exact(v0); v1 = gelu_exact(v1); }
                if (RES) {
                    float2 rv = *(const float2*)(resid + (size_t)row * N + col);
                    v0 += rv.x; v1 += rv.y;
                }
                if (OUT16) {
                    __half2 o2;
                    o2.x = __float2half_rn(v0);
                    o2.y = __float2half_rn(v1);
                    *(__half2*)((__half*)Cout + (size_t)row * N + col) = o2;
                } else {
                    float2 o2; o2.x = v0; o2.y = v1;
                    *(float2*)((float*)Cout + (size_t)row * N + col) = o2;
                }
            }
        }
    }
}

// ---------------- fp16 tensor-core flash attention ----------------
// 128 threads (4 warps), 64 q-rows per block, one (b,h). K/V fp16 tiles double-buffered.
__global__ void __launch_bounds__(128) attn_kernel(
    const __half* __restrict__ QKV, float* __restrict__ O)
{
    extern __shared__ __half smh[];
    __half* Ks = smh;                      // [2][64][AT_PADH]
    __half* Vs = smh + 2 * AT_TILEH;       // [2][64][AT_PADH]
    __half* Ps = smh + 4 * AT_TILEH;       // [64][AT_PADH]

    const int qt = blockIdx.x;
    const int bh = blockIdx.y;
    const int b  = bh >> 4;
    const int h  = bh & 15;
    const int tid  = threadIdx.x;
    const int lane = tid & 31;
    const int w    = tid >> 5;
    const int gr   = lane >> 2;
    const int tg   = lane & 3;

    const __half* Qb = QKV + (size_t)b * SEQ * QKV_LD + h * HDIMV;
    const __half* Kb = Qb + 1024;
    const __half* Vb = Qb + 2048;

    const uint32_t smb  = smem_u32(smh);
    const uint32_t KsB  = smb;
    const uint32_t VsB  = smb + 2 * AT_TILEH * 2;

    // ---- Q fragments straight from global (scaled by 1/8, exact in fp16) ----
    uint32_t qf[4][4];
    {
        const __half2 sc = __float2half2_rn(0.125f);
        const int r = qt * 64 + w * 16 + gr;
        #pragma unroll
        for (int kc = 0; kc < 4; kc++) {
            #pragma unroll
            for (int e = 0; e < 4; e++) {
                int rr = r + ((e & 1) ? 8 : 0);
                int dd = kc * 16 + ((e & 2) ? 8 : 0) + tg * 2;
                __half2 v = *(const __half2*)(Qb + (size_t)rr * QKV_LD + dd);
                v = __hmul2(v, sc);
                qf[kc][e] = *(uint32_t*)&v;
            }
        }
    }

    // ---- prologue: load K/V tile 0 (64 rows x 128 B each) ----
    #pragma unroll
    for (int j = 0; j < 4; j++) {
        int idx = j * 128 + tid;          // 0..511
        int r  = idx >> 3;
        int c8 = (idx & 7) * 8;           // half offset
        uint32_t doff = (r * AT_PADH + c8) * 2;
        cp_async16(KsB + doff, Kb + (size_t)r * QKV_LD + c8);
        cp_async16(VsB + doff, Vb + (size_t)r * QKV_LD + c8);
    }
    CP_COMMIT();

    float oacc[8][4] = {};
    float rm[2] = { -3e38f, -3e38f };
    float rl[2] = { 0.f, 0.f };

    for (int kt = 0; kt <= qt; kt++) {
        const int buf = kt & 1;
        if (kt < qt) {
            const int nbuf = (kt + 1) & 1;
            const size_t krow0 = (size_t)(kt + 1) * 64;
            #pragma unroll
            for (int j = 0; j < 4; j++) {
                int idx = j * 128 + tid;
                int r  = idx >> 3;
                int c8 = (idx & 7) * 8;
                uint32_t doff = (nbuf * AT_TILEH + r * AT_PADH + c8) * 2;
                cp_async16(KsB + doff, Kb + (krow0 + r) * QKV_LD + c8);
                cp_async16(VsB + doff, Vb + (krow0 + r) * QKV_LD + c8);
            }
            CP_COMMIT();
            CP_WAIT1();
        } else {
            CP_WAIT0();
        }
        __syncthreads();

        const __half* Kt = Ks + buf * AT_TILEH;
        const __half* Vt = Vs + buf * AT_TILEH;

        // ---- S = Q @ K^T (fp16 mma, 32 mmas) ----
        float s[8][4] = {};
        #pragma unroll
        for (int kc = 0; kc < 4; kc++) {
            uint32_t bf[8][2];
            #pragma unroll
            for (int nb = 0; nb < 8; nb++) {
                const __half* kp = Kt + (nb * 8 + gr) * AT_PADH + kc * 16 + tg * 2;
                bf[nb][0] = *(const uint32_t*)(kp);
                bf[nb][1] = *(const uint32_t*)(kp + 8);
            }
            #pragma unroll
            for (int nb = 0; nb < 8; nb++)
                mma_f16(s[nb], qf[kc], bf[nb]);
        }

        // ---- causal mask on diagonal tile ----
        if (kt == qt) {
            #pragma unroll
            for (int nb = 0; nb < 8; nb++)
                #pragma unroll
                for (int e = 0; e < 4; e++) {
                    int row = w * 16 + gr + (e >> 1) * 8;
                    int col = nb * 8 + tg * 2 + (e & 1);
                    if (col > row) s[nb][e] = -3e38f;
                }
        }

        // ---- online softmax (register stats, quad shuffle) ----
        float alpha[2];
        #pragma unroll
        for (int hh = 0; hh < 2; hh++) {
            float mloc = -3e38f;
            #pragma unroll
            for (int nb = 0; nb < 8; nb++) {
                mloc = fmaxf(mloc, s[nb][hh * 2 + 0]);
                mloc = fmaxf(mloc, s[nb][hh * 2 + 1]);
            }
            mloc = fmaxf(mloc, __shfl_xor_sync(0xffffffffu, mloc, 1));
            mloc = fmaxf(mloc, __shfl_xor_sync(0xffffffffu, mloc, 2));
            float mnew = fmaxf(rm[hh], mloc);
            alpha[hh] = __expf(rm[hh] - mnew);
            float suml = 0.f;
            #pragma unroll
            for (int nb = 0; nb < 8; nb++) {
                float p0 = __expf(s[nb][hh * 2 + 0] - mnew);
                float p1 = __expf(s[nb][hh * 2 + 1] - mnew);
                s[nb][hh * 2 + 0] = p0;
                s[nb][hh * 2 + 1] = p1;
                suml += p0 + p1;
            }
            suml += __shfl_xor_sync(0xffffffffu, suml, 1);
            suml += __shfl_xor_sync(0xffffffffu, suml, 2);
            rl[hh] = rl[hh] * alpha[hh] + suml;
            rm[hh] = mnew;
        }

        #pragma unroll
        for (int nb = 0; nb < 8; nb++) {
            oacc[nb][0] *= alpha[0]; oacc[nb][1] *= alpha[0];
            oacc[nb][2] *= alpha[1]; oacc[nb][3] *= alpha[1];
        }

        // ---- pack P (fp16) into smem strip ----
        {
            const int r0s = w * 16 + gr;
            #pragma unroll
            for (int nb = 0; nb < 8; nb++) {
                *(__half2*)(Ps + (r0s)     * AT_PADH + nb * 8 + tg * 2) =
                    __floats2half2_rn(s[nb][0], s[nb][1]);
                *(__half2*)(Ps + (r0s + 8) * AT_PADH + nb * 8 + tg * 2) =
                    __floats2half2_rn(s[nb][2], s[nb][3]);
            }
        }
        __syncwarp();

        // ---- O += P @ V (fp16 mma, 32 mmas) ----
        {
            const int r = w * 16 + gr;
            #pragma unroll
            for (int kc = 0; kc < 4; kc++) {
                uint32_t af[4];
                af[0] = *(const uint32_t*)(Ps + (r)     * AT_PADH + kc * 16 + tg * 2);
                af[1] = *(const uint32_t*)(Ps + (r + 8) * AT_PADH + kc * 16 + tg * 2);
                af[2] = *(const uint32_t*)(Ps + (r)     * AT_PADH + kc * 16 + 8 + tg * 2);
                af[3] = *(const uint32_t*)(Ps + (r + 8) * AT_PADH + kc * 16 + 8 + tg * 2);
                uint32_t bf[8][2];
                #pragma unroll
                for (int nb = 0; nb < 8; nb++) {
                    int d = nb * 8 + gr;
                    int t0 = kc * 16 + tg * 2;
                    __half2 b0 = __halves2half2(Vt[(t0)     * AT_PADH + d],
                                                Vt[(t0 + 1) * AT_PADH + d]);
                    __half2 b1 = __halves2half2(Vt[(t0 + 8) * AT_PADH + d],
                                                Vt[(t0 + 9) * AT_PADH + d]);
                    bf[nb][0] = *(uint32_t*)&b0;
                    bf[nb][1] = *(uint32_t*)&b1;
                }
                #pragma unroll
                for (int nb = 0; nb < 8; nb++)
                    mma_f16(oacc[nb], af, bf[nb]);
            }
        }
        __syncthreads();   // protect K/V/P buffers before next iteration's loads
    }

    // ---- normalize + write (concat-head layout) ----
    float linv0 = 1.0f / rl[0];
    float linv1 = 1.0f / rl[1];
    #pragma unroll
    for (int hh = 0; hh < 2; hh++) {
        size_t row = (size_t)b * SEQ + (size_t)(qt * 64 + w * 16 + gr + hh * 8);
        float linv = hh ? linv1 : linv0;
        #pragma unroll
        for (int nb = 0; nb < 8; nb++) {
            float2 o2;
            o2.x = oacc[nb][hh * 2 + 0] * linv;
            o2.y = oacc[nb][hh * 2 + 1] * linv;
            *(float2*)(O + row * DIMV + h * HDIMV + nb * 8 + tg * 2) = o2;
        }
    }
}

extern "C" void kernel_launch(void* const* d_in, const int* in_sizes, int n_in,
                              void* d_out, int out_size)
{
    const float* x    = (const float*)d_in[0];
    const float* ln1g = (const float*)d_in[1];
    const float* ln1b = (const float*)d_in[2];
    const float* Wq   = (const float*)d_in[3];
    const float* bq   = (const float*)d_in[4];
    const float* Wk   = (const float*)d_in[5];
    const float* bk   = (const float*)d_in[6];
    const float* Wv   = (const float*)d_in[7];
    const float* bv   = (const float*)d_in[8];
    const float* ln2g = (const float*)d_in[9];
    const float* ln2b = (const float*)d_in[10];
    const float* fclg = (const float*)d_in[11];
    const float* fclb = (const float*)d_in[12];
    const float* W1   = (const float*)d_in[13];
    const float* b1   = (const float*)d_in[14];
    const float* W2   = (const float*)d_in[15];
    const float* b2   = (const float*)d_in[16];
    float* out = (float*)d_out;

    float *p_o, *p_x2, *p_bqkv;
    __half *p_h, *p_qkv, *p_h2, *p_mid, *p_wt, *p_w1t, *p_w2t;
    cudaGetSymbolAddress((void**)&p_h,    g_h);
    cudaGetSymbolAddress((void**)&p_qkv,  g_qkv);
    cudaGetSymbolAddress((void**)&p_o,    g_o);
    cudaGetSymbolAddress((void**)&p_x2,   g_x2);
    cudaGetSymbolAddress((void**)&p_h2,   g_h2);
    cudaGetSymbolAddress((void**)&p_mid,  g_mid);
    cudaGetSymbolAddress((void**)&p_wt,   g_wt);
    cudaGetSymbolAddress((void**)&p_w1t,  g_w1t);
    cudaGetSymbolAddress((void**)&p_w2t,  g_w2t);
    cudaGetSymbolAddress((void**)&p_bqkv, g_bqkv);

    cudaFuncSetAttribute(attn_kernel, cudaFuncAttributeMaxDynamicSharedMemorySize, ATTN_SMEM_B);
    cudaFuncSetAttribute(gemm_f16<0,0,1>, cudaFuncAttributeMaxDynamicSharedMemorySize, GEMM_SMEM_BYTES);
    cudaFuncSetAttribute(gemm_f16<1,0,1>, cudaFuncAttributeMaxDynamicSharedMemorySize, GEMM_SMEM_BYTES);
    cudaFuncSetAttribute(gemm_f16<1,1,0>, cudaFuncAttributeMaxDynamicSharedMemorySize, GEMM_SMEM_BYTES);

    transpose_qkv_kernel<<<dim3(2, 32, 48), dim3(32, 8)>>>(Wq, Wk, Wv, p_wt);
    transpose_kernel_h16<<<dim3(HIDV / 32, DIMV / 32), dim3(32, 8)>>>(W1, p_w1t, DIMV, HIDV);
    transpose_kernel_h16<<<dim3(DIMV / 32, HIDV / 32), dim3(32, 8)>>>(W2, p_w2t, HIDV, DIMV);
    pack_bias_kernel<<<QKV_LD / 256, 256>>>(bq, bk, bv, p_bqkv);
    ln_kernel<<<NTOK, 256>>>(x, ln1g, ln1b, p_h);
    // QKV projection (fp16 in/out)
    gemm_f16<0,0,1><<<dim3(QKV_LD / BN, NTOK / BM), 256, GEMM_SMEM_BYTES>>>(
        p_h, p_wt, p_bqkv, nullptr, p_qkv, QKV_LD, DIMV);
    attn_kernel<<<dim3(SEQ / 64, 64), 128, ATTN_SMEM_B>>>(p_qkv, p_o);
    add_dln_kernel<<<NTOK, 256>>>(x, p_o, ln2g, ln2b, fclg, fclb, p_x2, p_h2);
    gemm_f16<1,0,1><<<dim3(HIDV / BN, NTOK / BM), 256, GEMM_SMEM_BYTES>>>(
        p_h2, p_w1t, b1, nullptr, p_mid, HIDV, DIMV);
    gemm_f16<1,1,0><<<dim3(DIMV / BN, NTOK / BM), 256, GEMM_SMEM_BYTES>>>(
        p_mid, p_w2t, b2, p_x2, out, DIMV, HIDV);
}

// round 11
// speedup vs baseline: 1.0675x; 1.0675x over previous
#include <cuda_runtime.h>
#include <cuda_fp16.h>
#include <cstdint>
#include <cstddef>

// Problem dims
#define DIMV   1024
#define HIDV   4096
#define SEQ    2048
#define NHEAD  16
#define HDIMV  64
#define NTOK   8192          // B * S
#define QKV_LD 3072          // fused QKV row stride

// GEMM tiling (fp16 mma m16n8k16): 128x128 tile, 32 K per stage
#define BM 128
#define BN 128
#define BKS16 32
#define TILE_H 2560          // 128 rows * 20 b32 (40 halves padded)
#define STAGE_H 5120
#define GEMM_SMEM_BYTES (3 * STAGE_H * 4)   // 61440

// attention smem (fp16 tiles, no P buffer)
#define AT_PADH 72                         // halves per row (64 + 8 pad)
#define AT_TILEH (64 * AT_PADH)            // halves per tile
#define ATTN_SMEM_B (4 * AT_TILEH * 2)     // K[2]+V[2] = 36864 B

// ---------------- static scratch ----------------
__device__ __half g_h  [(size_t)NTOK * DIMV];     // ln1(x) fp16
__device__ __half g_qkv[(size_t)NTOK * QKV_LD];   // fused Q|K|V fp16
__device__ float  g_o  [(size_t)NTOK * DIMV];
__device__ float  g_x2 [(size_t)NTOK * DIMV];
__device__ __half g_h2 [(size_t)NTOK * DIMV];
__device__ __half g_mid[(size_t)NTOK * HIDV];
__device__ __half g_wt [(size_t)QKV_LD * DIMV];
__device__ __half g_w1t[(size_t)HIDV * DIMV];
__device__ __half g_w2t[(size_t)DIMV * HIDV];
__device__ float  g_bqkv[QKV_LD];

// ---------------- helpers ----------------
__device__ __forceinline__ uint32_t smem_u32(const void* p) {
    uint32_t a;
    asm("{ .reg .u64 t; cvta.to.shared.u64 t, %1; cvt.u32.u64 %0, t; }" : "=r"(a) : "l"(p));
    return a;
}

__device__ __forceinline__ float gelu_exact(float x) {
    return 0.5f * x * (1.0f + erff(x * 0.70710678118654752f));
}

__device__ __forceinline__ void cp_async16(uint32_t dst, const void* src) {
    asm volatile("cp.async.cg.shared.global [%0], [%1], 16;" :: "r"(dst), "l"(src));
}
#define CP_COMMIT() asm volatile("cp.async.commit_group;" ::: "memory")
#define CP_WAIT1()  asm volatile("cp.async.wait_group 1;" ::: "memory")
#define CP_WAIT0()  asm volatile("cp.async.wait_group 0;" ::: "memory")

__device__ __forceinline__ void mma_f16(float* c, const uint32_t* a, const uint32_t* b) {
    asm volatile(
        "mma.sync.aligned.m16n8k16.row.col.f32.f16.f16.f32 "
        "{%0,%1,%2,%3}, {%4,%5,%6,%7}, {%8,%9}, {%0,%1,%2,%3};"
        : "+f"(c[0]), "+f"(c[1]), "+f"(c[2]), "+f"(c[3])
        : "r"(a[0]), "r"(a[1]), "r"(a[2]), "r"(a[3]), "r"(b[0]), "r"(b[1]));
}

__device__ __forceinline__ void ldsm_x4(uint32_t addr, uint32_t& r0, uint32_t& r1,
                                        uint32_t& r2, uint32_t& r3) {
    asm volatile("ldmatrix.sync.aligned.m8n8.x4.shared.b16 {%0,%1,%2,%3}, [%4];"
        : "=r"(r0), "=r"(r1), "=r"(r2), "=r"(r3) : "r"(addr));
}

__device__ __forceinline__ void ldsm_x4_t(uint32_t addr, uint32_t& r0, uint32_t& r1,
                                          uint32_t& r2, uint32_t& r3) {
    asm volatile("ldmatrix.sync.aligned.m8n8.x4.trans.shared.b16 {%0,%1,%2,%3}, [%4];"
        : "=r"(r0), "=r"(r1), "=r"(r2), "=r"(r3) : "r"(addr));
}

// ---------------- weight transposes (fp16 output) ----------------
__global__ void transpose_kernel_h16(const float* __restrict__ src, __half* __restrict__ dst,
                                     int R, int C)
{
    __shared__ float t[32][33];
    int c0 = blockIdx.x * 32, r0 = blockIdx.y * 32;
    int tx = threadIdx.x, ty = threadIdx.y;
    #pragma unroll
    for (int i = 0; i < 32; i += 8)
        t[ty + i][tx] = src[(size_t)(r0 + ty + i) * C + c0 + tx];
    __syncthreads();
    #pragma unroll
    for (int i = 0; i < 32; i += 8)
        dst[(size_t)(c0 + ty + i) * R + r0 + tx] = __float2half_rn(t[tx][ty + i]);
}

__global__ void transpose_qkv_kernel(const float* __restrict__ Wq, const float* __restrict__ Wk,
                                     const float* __restrict__ Wv, __half* __restrict__ dst)
{
    __shared__ float t[32][33];
    int s = blockIdx.z, w = s >> 4, h = s & 15;
    const float* W = ((w == 0) ? Wq : (w == 1) ? Wk : Wv) + (size_t)h * DIMV * HDIMV;
    __half* D = dst + (size_t)(w * 1024 + h * 64) * DIMV;
    int c0 = blockIdx.x * 32, r0 = blockIdx.y * 32;
    int tx = threadIdx.x, ty = threadIdx.y;
    #pragma unroll
    for (int i = 0; i < 32; i += 8)
        t[ty + i][tx] = W[(size_t)(r0 + ty + i) * HDIMV + c0 + tx];
    __syncthreads();
    #pragma unroll
    for (int i = 0; i < 32; i += 8)
        D[(size_t)(c0 + ty + i) * DIMV + r0 + tx] = __float2half_rn(t[tx][ty + i]);
}

__global__ void pack_bias_kernel(const float* __restrict__ bq, const float* __restrict__ bk,
                                 const float* __restrict__ bv, float* __restrict__ dst)
{
    int i = blockIdx.x * 256 + threadIdx.x;
    float v = (i < 1024) ? bq[i] : (i < 2048) ? bk[i - 1024] : bv[i - 2048];
    dst[i] = v;
}

// ---------------- LayerNorm (fp16 output) ----------------
__global__ void ln_kernel(const float* __restrict__ x, const float* __restrict__ g,
                          const float* __restrict__ b, __half* __restrict__ y)
{
    __shared__ float s_a[8], s_b[8];
    __shared__ float s_mu, s_rs;
    size_t row = blockIdx.x;
    int tid = threadIdx.x;
    float4 v = ((const float4*)(x + row * DIMV))[tid];
    float sum = v.x + v.y + v.z + v.w;
    float sq  = v.x*v.x + v.y*v.y + v.z*v.z + v.w*v.w;
    #pragma unroll
    for (int o = 16; o; o >>= 1) {
        sum += __shfl_xor_sync(0xffffffffu, sum, o);
        sq  += __shfl_xor_sync(0xffffffffu, sq,  o);
    }
    if ((tid & 31) == 0) { s_a[tid >> 5] = sum; s_b[tid >> 5] = sq; }
    __syncthreads();
    if (tid == 0) {
        float ts = 0.f, tq = 0.f;
        #pragma unroll
        for (int i = 0; i < 8; i++) { ts += s_a[i]; tq += s_b[i]; }
        float mu  = ts * (1.0f / DIMV);
        float var = tq * (1.0f / DIMV) - mu * mu;
        s_mu = mu; s_rs = rsqrtf(var + 1e-5f);
    }
    __syncthreads();
    float mu = s_mu, rs = s_rs;
    float4 gv = ((const float4*)g)[tid];
    float4 bv = ((const float4*)b)[tid];
    __half2 h0, h1;
    h0.x = __float2half_rn((v.x - mu) * rs * gv.x + bv.x);
    h0.y = __float2half_rn((v.y - mu) * rs * gv.y + bv.y);
    h1.x = __float2half_rn((v.z - mu) * rs * gv.z + bv.z);
    h1.y = __float2half_rn((v.w - mu) * rs * gv.w + bv.w);
    ((__half2*)(y + row * DIMV))[tid * 2 + 0] = h0;
    ((__half2*)(y + row * DIMV))[tid * 2 + 1] = h1;
}

// ---------------- residual add + LN(ln2) + LN(fcln), h2 out fp16 ----------------
__global__ void add_dln_kernel(const float* __restrict__ x, const float* __restrict__ oatt,
                               const float* __restrict__ g2, const float* __restrict__ b2,
                               const float* __restrict__ gf, const float* __restrict__ bf,
                               float* __restrict__ x2, __half* __restrict__ h2)
{
    __shared__ float s_a[8], s_b[8];
    __shared__ float s_mu, s_rs;
    size_t row = blockIdx.x;
    int tid = threadIdx.x;
    float4 v  = ((const float4*)(x    + row * DIMV))[tid];
    float4 ov = ((const float4*)(oatt + row * DIMV))[tid];
    v.x += ov.x; v.y += ov.y; v.z += ov.z; v.w += ov.w;
    ((float4*)(x2 + row * DIMV))[tid] = v;

    float sum = v.x + v.y + v.z + v.w;
    float sq  = v.x*v.x + v.y*v.y + v.z*v.z + v.w*v.w;
    #pragma unroll
    for (int o = 16; o; o >>= 1) {
        sum += __shfl_xor_sync(0xffffffffu, sum, o);
        sq  += __shfl_xor_sync(0xffffffffu, sq,  o);
    }
    if ((tid & 31) == 0) { s_a[tid >> 5] = sum; s_b[tid >> 5] = sq; }
    __syncthreads();
    if (tid == 0) {
        float ts = 0.f, tq = 0.f;
        #pragma unroll
        for (int i = 0; i < 8; i++) { ts += s_a[i]; tq += s_b[i]; }
        float mu  = ts * (1.0f / DIMV);
        float var = tq * (1.0f / DIMV) - mu * mu;
        s_mu = mu; s_rs = rsqrtf(var + 1e-5f);
    }
    __syncthreads();
    float mu1 = s_mu, rs1 = s_rs;
    float4 g2v = ((const float4*)g2)[tid];
    float4 b2v = ((const float4*)b2)[tid];
    float4 t;
    t.x = (v.x - mu1) * rs1 * g2v.x + b2v.x;
    t.y = (v.y - mu1) * rs1 * g2v.y + b2v.y;
    t.z = (v.z - mu1) * rs1 * g2v.z + b2v.z;
    t.w = (v.w - mu1) * rs1 * g2v.w + b2v.w;

    float sum2 = t.x + t.y + t.z + t.w;
    float sq2  = t.x*t.x + t.y*t.y + t.z*t.z + t.w*t.w;
    #pragma unroll
    for (int o = 16; o; o >>= 1) {
        sum2 += __shfl_xor_sync(0xffffffffu, sum2, o);
        sq2  += __shfl_xor_sync(0xffffffffu, sq2,  o);
    }
    if ((tid & 31) == 0) { s_a[tid >> 5] = sum2; s_b[tid >> 5] = sq2; }
    __syncthreads();
    if (tid == 0) {
        float ts = 0.f, tq = 0.f;
        #pragma unroll
        for (int i = 0; i < 8; i++) { ts += s_a[i]; tq += s_b[i]; }
        float mu  = ts * (1.0f / DIMV);
        float var = tq * (1.0f / DIMV) - mu * mu;
        s_mu = mu; s_rs = rsqrtf(var + 1e-5f);
    }
    __syncthreads();
    float mu2 = s_mu, rs2 = s_rs;
    float4 gfv = ((const float4*)gf)[tid];
    float4 bfv = ((const float4*)bf)[tid];
    __half2 h0, h1;
    h0.x = __float2half_rn((t.x - mu2) * rs2 * gfv.x + bfv.x);
    h0.y = __float2half_rn((t.y - mu2) * rs2 * gfv.y + bfv.y);
    h1.x = __float2half_rn((t.z - mu2) * rs2 * gfv.z + bfv.z);
    h1.y = __float2half_rn((t.w - mu2) * rs2 * gfv.w + bfv.w);
    ((__half2*)(h2 + row * DIMV))[tid * 2 + 0] = h0;
    ((__half2*)(h2 + row * DIMV))[tid * 2 + 1] = h1;
}

// ---------------- fp16 GEMM with ldmatrix fragment loads ----------------
template<int ACT, int RES, int OUT16>
__global__ void __launch_bounds__(256) gemm_f16(
    const __half* __restrict__ A, const __half* __restrict__ Bt,
    const float* __restrict__ bias, const float* __restrict__ resid,
    void* __restrict__ Cout, int N, int K)
{
    extern __shared__ float sm[];
    const int tid  = threadIdx.x;
    const int lane = tid & 31;
    const int warp = tid >> 5;
    const int wm = warp >> 2;
    const int wn = warp & 3;
    const int m0 = blockIdx.y * BM;
    const int n0 = blockIdx.x * BN;
    const int KT = K / BKS16;

    const int lrow = tid >> 2;
    const int lk8  = (tid & 3) * 8;
    const int lk4  = (tid & 3) * 4;

    const __half* Asrc0 = A  + (size_t)(m0 + lrow)      * K + lk8;
    const __half* Asrc1 = A  + (size_t)(m0 + lrow + 64) * K + lk8;
    const __half* Bsrc0 = Bt + (size_t)(n0 + lrow)      * K + lk8;
    const __half* Bsrc1 = Bt + (size_t)(n0 + lrow + 64) * K + lk8;

    const uint32_t smb = smem_u32(sm);
    const uint32_t dA0 = smb + ((lrow)      * 20 + lk4) * 4;
    const uint32_t dA1 = smb + ((lrow + 64) * 20 + lk4) * 4;
    const uint32_t dB0 = dA0 + TILE_H * 4;
    const uint32_t dB1 = dA1 + TILE_H * 4;

    // ldmatrix lane offsets (bytes from tile base; row stride 80 B)
    const uint32_t aOff = (uint32_t)(wm * 64 + (lane & 15)) * 80 + ((lane >> 4) * 8) * 2;
    const uint32_t bOff = (uint32_t)(wn * 32 + (lane & 7) + ((lane >> 4) * 8)) * 80
                        + (((lane >> 3) & 1) * 8) * 2;

    #pragma unroll
    for (int s = 0; s < 2; s++) {
        uint32_t off = s * STAGE_H * 4;
        int k0 = s * BKS16;
        cp_async16(dA0 + off, Asrc0 + k0);
        cp_async16(dA1 + off, Asrc1 + k0);
        cp_async16(dB0 + off, Bsrc0 + k0);
        cp_async16(dB1 + off, Bsrc1 + k0);
        CP_COMMIT();
    }

    float acc[4][4][4] = {};
    const int gr = lane >> 2;
    const int tg = lane & 3;

    for (int kt = 0; kt < KT; kt++) {
        CP_WAIT1();
        __syncthreads();
        const uint32_t stage = smb + (kt % 3) * STAGE_H * 4;
        const uint32_t aBase = stage + aOff;
        const uint32_t bBase = stage + TILE_H * 4 + bOff;

        #pragma unroll
        for (int kc = 0; kc < 2; kc++) {
            uint32_t af[4][4], bf[4][2];
            #pragma unroll
            for (int mb = 0; mb < 4; mb++)
                ldsm_x4(aBase + mb * 1280 + kc * 32,
                        af[mb][0], af[mb][1], af[mb][2], af[mb][3]);
            #pragma unroll
            for (int p = 0; p < 2; p++)
                ldsm_x4(bBase + p * 1280 + kc * 32,
                        bf[2*p][0], bf[2*p][1], bf[2*p+1][0], bf[2*p+1][1]);
            #pragma unroll
            for (int mb = 0; mb < 4; mb++)
                #pragma unroll
                for (int nb = 0; nb < 4; nb++)
                    mma_f16(acc[mb][nb], af[mb], bf[nb]);
        }

        if (kt + 2 < KT) {
            uint32_t off = ((kt + 2) % 3) * STAGE_H * 4;
            int k0 = (kt + 2) * BKS16;
            cp_async16(dA0 + off, Asrc0 + k0);
            cp_async16(dA1 + off, Asrc1 + k0);
            cp_async16(dB0 + off, Bsrc0 + k0);
            cp_async16(dB1 + off, Bsrc1 + k0);
        }
        CP_COMMIT();
        __syncthreads();
    }

    #pragma unroll
    for (int mb = 0; mb < 4; mb++) {
        int rlo = m0 + wm * 64 + mb * 16 + gr;
        #pragma unroll
        for (int nb = 0; nb < 4; nb++) {
            int col = n0 + wn * 32 + nb * 8 + tg * 2;
            float2 bi = *(const float2*)(bias + col);
            #pragma unroll
            for (int half_i = 0; half_i < 2; half_i++) {
                int row = rlo + half_i * 8;
                float v0 = acc[mb][nb][half_i * 2 + 0] + bi.x;
                float v1 = acc[mb][nb][half_i * 2 + 1] + bi.y;
                if (ACT) { v0 = gelu_exact(v0); v1 = gelu_exact(v1); }
                if (RES) {
                    float2 rv = *(const float2*)(resid + (size_t)row * N + col);
                    v0 += rv.x; v1 += rv.y;
                }
                if (OUT16) {
                    __half2 o2;
                    o2.x = __float2half_rn(v0);
                    o2.y = __float2half_rn(v1);
                    *(__half2*)((__half*)Cout + (size_t)row * N + col) = o2;
                } else {
                    float2 o2; o2.x = v0; o2.y = v1;
                    *(float2*)((float*)Cout + (size_t)row * N + col) = o2;
                }
            }
        }
    }
}

// ---------------- fp16 flash attention (ldmatrix K/V, register P) ----------------
__global__ void __launch_bounds__(128) attn_kernel(
    const __half* __restrict__ QKV, float* __restrict__ O)
{
    extern __shared__ __half smh[];
    // layout: K[2][64][AT_PADH], V[2][64][AT_PADH]

    const int qt = blockIdx.x;
    const int bh = blockIdx.y;
    const int b  = bh >> 4;
    const int h  = bh & 15;
    const int tid  = threadIdx.x;
    const int lane = tid & 31;
    const int w    = tid >> 5;
    const int gr   = lane >> 2;
    const int tg   = lane & 3;

    const __half* Qb = QKV + (size_t)b * SEQ * QKV_LD + h * HDIMV;
    const __half* Kb = Qb + 1024;
    const __half* Vb = Qb + 2048;

    const uint32_t smb = smem_u32(smh);
    const uint32_t KsB = smb;
    const uint32_t VsB = smb + 2 * AT_TILEH * 2;

    // ldmatrix lane offsets (row stride = AT_PADH*2 = 144 B)
    const uint32_t kOff = (uint32_t)((lane & 7) + ((lane >> 4) * 8)) * (AT_PADH * 2)
                        + (((lane >> 3) & 1) * 8) * 2;
    const uint32_t vOff = (uint32_t)((lane & 7) + (((lane >> 3) & 1) * 8)) * (AT_PADH * 2)
                        + ((lane >> 4) * 8) * 2;

    // ---- Q fragments straight from global (scaled by 1/8, exact in fp16) ----
    uint32_t qf[4][4];
    {
        const __half2 sc = __float2half2_rn(0.125f);
        const int r = qt * 64 + w * 16 + gr;
        #pragma unroll
        for (int kc = 0; kc < 4; kc++) {
            #pragma unroll
            for (int e = 0; e < 4; e++) {
                int rr = r + ((e & 1) ? 8 : 0);
                int dd = kc * 16 + ((e & 2) ? 8 : 0) + tg * 2;
                __half2 v = *(const __half2*)(Qb + (size_t)rr * QKV_LD + dd);
                v = __hmul2(v, sc);
                qf[kc][e] = *(uint32_t*)&v;
            }
        }
    }

    // ---- prologue: load K/V tile 0 ----
    #pragma unroll
    for (int j = 0; j < 4; j++) {
        int idx = j * 128 + tid;
        int r  = idx >> 3;
        int c8 = (idx & 7) * 8;
        uint32_t doff = (r * AT_PADH + c8) * 2;
        cp_async16(KsB + doff, Kb + (size_t)r * QKV_LD + c8);
        cp_async16(VsB + doff, Vb + (size_t)r * QKV_LD + c8);
    }
    CP_COMMIT();

    float oacc[8][4] = {};
    float rm[2] = { -3e38f, -3e38f };
    float rl[2] = { 0.f, 0.f };

    for (int kt = 0; kt <= qt; kt++) {
        const int buf = kt & 1;
        if (kt < qt) {
            const int nbuf = (kt + 1) & 1;
            const size_t krow0 = (size_t)(kt + 1) * 64;
            #pragma unroll
            for (int j = 0; j < 4; j++) {
                int idx = j * 128 + tid;
                int r  = idx >> 3;
                int c8 = (idx & 7) * 8;
                uint32_t doff = (nbuf * AT_TILEH + r * AT_PADH + c8) * 2;
                cp_async16(KsB + doff, Kb + (krow0 + r) * QKV_LD + c8);
                cp_async16(VsB + doff, Vb + (krow0 + r) * QKV_LD + c8);
            }
            CP_COMMIT();
            CP_WAIT1();
        } else {
            CP_WAIT0();
        }
        __syncthreads();

        const uint32_t KtB = KsB + buf * AT_TILEH * 2 + kOff;
        const uint32_t VtB = VsB + buf * AT_TILEH * 2 + vOff;

        // ---- S = Q @ K^T (ldmatrix K B-frags) ----
        float s[8][4] = {};
        #pragma unroll
        for (int kc = 0; kc < 4; kc++) {
            uint32_t bf[8][2];
            #pragma unroll
            for (int p = 0; p < 4; p++)
                ldsm_x4(KtB + p * 16 * (AT_PADH * 2) + kc * 32,
                        bf[2*p][0], bf[2*p][1], bf[2*p+1][0], bf[2*p+1][1]);
            #pragma unroll
            for (int nb = 0; nb < 8; nb++)
                mma_f16(s[nb], qf[kc], bf[nb]);
        }

        // ---- causal mask on diagonal tile ----
        if (kt == qt) {
            #pragma unroll
            for (int nb = 0; nb < 8; nb++)
                #pragma unroll
                for (int e = 0; e < 4; e++) {
                    int row = w * 16 + gr + (e >> 1) * 8;
                    int col = nb * 8 + tg * 2 + (e & 1);
                    if (col > row) s[nb][e] = -3e38f;
                }
        }

        // ---- online softmax (register stats, quad shuffle) ----
        float alpha[2];
        #pragma unroll
        for (int hh = 0; hh < 2; hh++) {
            float mloc = -3e38f;
            #pragma unroll
            for (int nb = 0; nb < 8; nb++) {
                mloc = fmaxf(mloc, s[nb][hh * 2 + 0]);
                mloc = fmaxf(mloc, s[nb][hh * 2 + 1]);
            }
            mloc = fmaxf(mloc, __shfl_xor_sync(0xffffffffu, mloc, 1));
            mloc = fmaxf(mloc, __shfl_xor_sync(0xffffffffu, mloc, 2));
            float mnew = fmaxf(rm[hh], mloc);
            alpha[hh] = __expf(rm[hh] - mnew);
            float suml = 0.f;
            #pragma unroll
            for (int nb = 0; nb < 8; nb++) {
                float p0 = __expf(s[nb][hh * 2 + 0] - mnew);
                float p1 = __expf(s[nb][hh * 2 + 1] - mnew);
                s[nb][hh * 2 + 0] = p0;
                s[nb][hh * 2 + 1] = p1;
                suml += p0 + p1;
            }
            suml += __shfl_xor_sync(0xffffffffu, suml, 1);
            suml += __shfl_xor_sync(0xffffffffu, suml, 2);
            rl[hh] = rl[hh] * alpha[hh] + suml;
            rm[hh] = mnew;
        }

        #pragma unroll
        for (int nb = 0; nb < 8; nb++) {
            oacc[nb][0] *= alpha[0]; oacc[nb][1] *= alpha[0];
            oacc[nb][2] *= alpha[1]; oacc[nb][3] *= alpha[1];
        }

        // ---- O += P @ V : A-frags packed from S registers, V via ldmatrix.trans ----
        #pragma unroll
        for (int kc = 0; kc < 4; kc++) {
            uint32_t af[4];
            {
                __half2 a0 = __floats2half2_rn(s[2*kc][0],   s[2*kc][1]);
                __half2 a1 = __floats2half2_rn(s[2*kc][2],   s[2*kc][3]);
                __half2 a2 = __floats2half2_rn(s[2*kc+1][0], s[2*kc+1][1]);
                __half2 a3 = __floats2half2_rn(s[2*kc+1][2], s[2*kc+1][3]);
                af[0] = *(uint32_t*)&a0; af[1] = *(uint32_t*)&a1;
                af[2] = *(uint32_t*)&a2; af[3] = *(uint32_t*)&a3;
            }
            uint32_t bf[8][2];
            #pragma unroll
            for (int p = 0; p < 4; p++)
                ldsm_x4_t(VtB + kc * 16 * (AT_PADH * 2) + p * 32,
                          bf[2*p][0], bf[2*p][1], bf[2*p+1][0], bf[2*p+1][1]);
            #pragma unroll
            for (int nb = 0; nb < 8; nb++)
                mma_f16(oacc[nb], af, bf[nb]);
        }
        __syncthreads();   // protect K/V buffers before next iteration's loads
    }

    // ---- normalize + write (concat-head layout) ----
    float linv0 = 1.0f / rl[0];
    float linv1 = 1.0f / rl[1];
    #pragma unroll
    for (int hh = 0; hh < 2; hh++) {
        size_t row = (size_t)b * SEQ + (size_t)(qt * 64 + w * 16 + gr + hh * 8);
        float linv = hh ? linv1 : linv0;
        #pragma unroll
        for (int nb = 0; nb < 8; nb++) {
            float2 o2;
            o2.x = oacc[nb][hh * 2 + 0] * linv;
            o2.y = oacc[nb][hh * 2 + 1] * linv;
            *(float2*)(O + row * DIMV + h * HDIMV + nb * 8 + tg * 2) = o2;
        }
    }
}

extern "C" void kernel_launch(void* const* d_in, const int* in_sizes, int n_in,
                              void* d_out, int out_size)
{
    const float* x    = (const float*)d_in[0];
    const float* ln1g = (const float*)d_in[1];
    const float* ln1b = (const float*)d_in[2];
    const float* Wq   = (const float*)d_in[3];
    const float* bq   = (const float*)d_in[4];
    const float* Wk   = (const float*)d_in[5];
    const float* bk   = (const float*)d_in[6];
    const float* Wv   = (const float*)d_in[7];
    const float* bv   = (const float*)d_in[8];
    const float* ln2g = (const float*)d_in[9];
    const float* ln2b = (const float*)d_in[10];
    const float* fclg = (const float*)d_in[11];
    const float* fclb = (const float*)d_in[12];
    const float* W1   = (const float*)d_in[13];
    const float* b1   = (const float*)d_in[14];
    const float* W2   = (const float*)d_in[15];
    const float* b2   = (const float*)d_in[16];
    float* out = (float*)d_out;

    float *p_o, *p_x2, *p_bqkv;
    __half *p_h, *p_qkv, *p_h2, *p_mid, *p_wt, *p_w1t, *p_w2t;
    cudaGetSymbolAddress((void**)&p_h,    g_h);
    cudaGetSymbolAddress((void**)&p_qkv,  g_qkv);
    cudaGetSymbolAddress((void**)&p_o,    g_o);
    cudaGetSymbolAddress((void**)&p_x2,   g_x2);
    cudaGetSymbolAddress((void**)&p_h2,   g_h2);
    cudaGetSymbolAddress((void**)&p_mid,  g_mid);
    cudaGetSymbolAddress((void**)&p_wt,   g_wt);
    cudaGetSymbolAddress((void**)&p_w1t,  g_w1t);
    cudaGetSymbolAddress((void**)&p_w2t,  g_w2t);
    cudaGetSymbolAddress((void**)&p_bqkv, g_bqkv);

    cudaFuncSetAttribute(attn_kernel, cudaFuncAttributeMaxDynamicSharedMemorySize, ATTN_SMEM_B);
    cudaFuncSetAttribute(gemm_f16<0,0,1>, cudaFuncAttributeMaxDynamicSharedMemorySize, GEMM_SMEM_BYTES);
    cudaFuncSetAttribute(gemm_f16<1,0,1>, cudaFuncAttributeMaxDynamicSharedMemorySize, GEMM_SMEM_BYTES);
    cudaFuncSetAttribute(gemm_f16<1,1,0>, cudaFuncAttributeMaxDynamicSharedMemorySize, GEMM_SMEM_BYTES);

    transpose_qkv_kernel<<<dim3(2, 32, 48), dim3(32, 8)>>>(Wq, Wk, Wv, p_wt);
    transpose_kernel_h16<<<dim3(HIDV / 32, DIMV / 32), dim3(32, 8)>>>(W1, p_w1t, DIMV, HIDV);
    transpose_kernel_h16<<<dim3(DIMV / 32, HIDV / 32), dim3(32, 8)>>>(W2, p_w2t, HIDV, DIMV);
    pack_bias_kernel<<<QKV_LD / 256, 256>>>(bq, bk, bv, p_bqkv);
    ln_kernel<<<NTOK, 256>>>(x, ln1g, ln1b, p_h);
    gemm_f16<0,0,1><<<dim3(QKV_LD / BN, NTOK / BM), 256, GEMM_SMEM_BYTES>>>(
        p_h, p_wt, p_bqkv, nullptr, p_qkv, QKV_LD, DIMV);
    attn_kernel<<<dim3(SEQ / 64, 64), 128, ATTN_SMEM_B>>>(p_qkv, p_o);
    add_dln_kernel<<<NTOK, 256>>>(x, p_o, ln2g, ln2b, fclg, fclb, p_x2, p_h2);
    gemm_f16<1,0,1><<<dim3(HIDV / BN, NTOK / BM), 256, GEMM_SMEM_BYTES>>>(
        p_h2, p_w1t, b1, nullptr, p_mid, HIDV, DIMV);
    gemm_f16<1,1,0><<<dim3(DIMV / BN, NTOK / BM), 256, GEMM_SMEM_BYTES>>>(
        p_mid, p_w2t, b2, p_x2, out, DIMV, HIDV);
}

// round 12
// speedup vs baseline: 1.1132x; 1.0429x over previous
#include <cuda_runtime.h>
#include <cuda_fp16.h>
#include <cstdint>
#include <cstddef>

// Problem dims
#define DIMV   1024
#define HIDV   4096
#define SEQ    2048
#define NHEAD  16
#define HDIMV  64
#define NTOK   8192          // B * S
#define QKV_LD 3072          // fused QKV row stride

// GEMM tiling (fp16 mma m16n8k16): 128x128 tile, 32 K per stage, 4 stages
#define BM 128
#define BN 128
#define BKS16 32
#define TILE_H 2560          // 128 rows * 20 b32 (40 halves padded)
#define STAGE_H 5120
#define NSTAGE 4
#define GEMM_SMEM_BYTES (NSTAGE * STAGE_H * 4)   // 81920

// attention: q-tile 128, k-tile 64, fp16 smem tiles (K/V double buffered)
#define AT_PADH 72                         // halves per row (64 + 8 pad)
#define AT_TILEH (64 * AT_PADH)            // halves per tile
#define ATTN_SMEM_B (4 * AT_TILEH * 2)     // K[2]+V[2] = 36864 B
#define BQ 128

// ---------------- static scratch ----------------
__device__ __half g_h  [(size_t)NTOK * DIMV];     // ln1(x) fp16
__device__ __half g_qkv[(size_t)NTOK * QKV_LD];   // fused Q|K|V fp16
__device__ float  g_o  [(size_t)NTOK * DIMV];
__device__ float  g_x2 [(size_t)NTOK * DIMV];
__device__ __half g_h2 [(size_t)NTOK * DIMV];
__device__ __half g_mid[(size_t)NTOK * HIDV];
__device__ __half g_wt [(size_t)QKV_LD * DIMV];
__device__ __half g_w1t[(size_t)HIDV * DIMV];
__device__ __half g_w2t[(size_t)DIMV * HIDV];
__device__ float  g_bqkv[QKV_LD];

// ---------------- helpers ----------------
__device__ __forceinline__ uint32_t smem_u32(const void* p) {
    uint32_t a;
    asm("{ .reg .u64 t; cvta.to.shared.u64 t, %1; cvt.u32.u64 %0, t; }" : "=r"(a) : "l"(p));
    return a;
}

__device__ __forceinline__ float gelu_exact(float x) {
    return 0.5f * x * (1.0f + erff(x * 0.70710678118654752f));
}

__device__ __forceinline__ void cp_async16(uint32_t dst, const void* src) {
    asm volatile("cp.async.cg.shared.global [%0], [%1], 16;" :: "r"(dst), "l"(src));
}
#define CP_COMMIT() asm volatile("cp.async.commit_group;" ::: "memory")
#define CP_WAIT2()  asm volatile("cp.async.wait_group 2;" ::: "memory")
#define CP_WAIT1()  asm volatile("cp.async.wait_group 1;" ::: "memory")
#define CP_WAIT0()  asm volatile("cp.async.wait_group 0;" ::: "memory")

__device__ __forceinline__ void mma_f16(float* c, const uint32_t* a, const uint32_t* b) {
    asm volatile(
        "mma.sync.aligned.m16n8k16.row.col.f32.f16.f16.f32 "
        "{%0,%1,%2,%3}, {%4,%5,%6,%7}, {%8,%9}, {%0,%1,%2,%3};"
        : "+f"(c[0]), "+f"(c[1]), "+f"(c[2]), "+f"(c[3])
        : "r"(a[0]), "r"(a[1]), "r"(a[2]), "r"(a[3]), "r"(b[0]), "r"(b[1]));
}

__device__ __forceinline__ void ldsm_x4(uint32_t addr, uint32_t& r0, uint32_t& r1,
                                        uint32_t& r2, uint32_t& r3) {
    asm volatile("ldmatrix.sync.aligned.m8n8.x4.shared.b16 {%0,%1,%2,%3}, [%4];"
        : "=r"(r0), "=r"(r1), "=r"(r2), "=r"(r3) : "r"(addr));
}

__device__ __forceinline__ void ldsm_x4_t(uint32_t addr, uint32_t& r0, uint32_t& r1,
                                          uint32_t& r2, uint32_t& r3) {
    asm volatile("ldmatrix.sync.aligned.m8n8.x4.trans.shared.b16 {%0,%1,%2,%3}, [%4];"
        : "=r"(r0), "=r"(r1), "=r"(r2), "=r"(r3) : "r"(addr));
}

// ---------------- weight transposes (fp16 output) ----------------
__global__ void transpose_kernel_h16(const float* __restrict__ src, __half* __restrict__ dst,
                                     int R, int C)
{
    __shared__ float t[32][33];
    int c0 = blockIdx.x * 32, r0 = blockIdx.y * 32;
    int tx = threadIdx.x, ty = threadIdx.y;
    #pragma unroll
    for (int i = 0; i < 32; i += 8)
        t[ty + i][tx] = src[(size_t)(r0 + ty + i) * C + c0 + tx];
    __syncthreads();
    #pragma unroll
    for (int i = 0; i < 32; i += 8)
        dst[(size_t)(c0 + ty + i) * R + r0 + tx] = __float2half_rn(t[tx][ty + i]);
}

__global__ void transpose_qkv_kernel(const float* __restrict__ Wq, const float* __restrict__ Wk,
                                     const float* __restrict__ Wv, __half* __restrict__ dst)
{
    __shared__ float t[32][33];
    int s = blockIdx.z, w = s >> 4, h = s & 15;
    const float* W = ((w == 0) ? Wq : (w == 1) ? Wk : Wv) + (size_t)h * DIMV * HDIMV;
    __half* D = dst + (size_t)(w * 1024 + h * 64) * DIMV;
    int c0 = blockIdx.x * 32, r0 = blockIdx.y * 32;
    int tx = threadIdx.x, ty = threadIdx.y;
    #pragma unroll
    for (int i = 0; i < 32; i += 8)
        t[ty + i][tx] = W[(size_t)(r0 + ty + i) * HDIMV + c0 + tx];
    __syncthreads();
    #pragma unroll
    for (int i = 0; i < 32; i += 8)
        D[(size_t)(c0 + ty + i) * DIMV + r0 + tx] = __float2half_rn(t[tx][ty + i]);
}

__global__ void pack_bias_kernel(const float* __restrict__ bq, const float* __restrict__ bk,
                                 const float* __restrict__ bv, float* __restrict__ dst)
{
    int i = blockIdx.x * 256 + threadIdx.x;
    float v = (i < 1024) ? bq[i] : (i < 2048) ? bk[i - 1024] : bv[i - 2048];
    dst[i] = v;
}

// ---------------- LayerNorm (fp16 output) ----------------
__global__ void ln_kernel(const float* __restrict__ x, const float* __restrict__ g,
                          const float* __restrict__ b, __half* __restrict__ y)
{
    __shared__ float s_a[8], s_b[8];
    __shared__ float s_mu, s_rs;
    size_t row = blockIdx.x;
    int tid = threadIdx.x;
    float4 v = ((const float4*)(x + row * DIMV))[tid];
    float sum = v.x + v.y + v.z + v.w;
    float sq  = v.x*v.x + v.y*v.y + v.z*v.z + v.w*v.w;
    #pragma unroll
    for (int o = 16; o; o >>= 1) {
        sum += __shfl_xor_sync(0xffffffffu, sum, o);
        sq  += __shfl_xor_sync(0xffffffffu, sq,  o);
    }
    if ((tid & 31) == 0) { s_a[tid >> 5] = sum; s_b[tid >> 5] = sq; }
    __syncthreads();
    if (tid == 0) {
        float ts = 0.f, tq = 0.f;
        #pragma unroll
        for (int i = 0; i < 8; i++) { ts += s_a[i]; tq += s_b[i]; }
        float mu  = ts * (1.0f / DIMV);
        float var = tq * (1.0f / DIMV) - mu * mu;
        s_mu = mu; s_rs = rsqrtf(var + 1e-5f);
    }
    __syncthreads();
    float mu = s_mu, rs = s_rs;
    float4 gv = ((const float4*)g)[tid];
    float4 bv = ((const float4*)b)[tid];
    __half2 h0, h1;
    h0.x = __float2half_rn((v.x - mu) * rs * gv.x + bv.x);
    h0.y = __float2half_rn((v.y - mu) * rs * gv.y + bv.y);
    h1.x = __float2half_rn((v.z - mu) * rs * gv.z + bv.z);
    h1.y = __float2half_rn((v.w - mu) * rs * gv.w + bv.w);
    ((__half2*)(y + row * DIMV))[tid * 2 + 0] = h0;
    ((__half2*)(y + row * DIMV))[tid * 2 + 1] = h1;
}

// ---------------- residual add + LN(ln2) + LN(fcln), h2 out fp16 ----------------
__global__ void add_dln_kernel(const float* __restrict__ x, const float* __restrict__ oatt,
                               const float* __restrict__ g2, const float* __restrict__ b2,
                               const float* __restrict__ gf, const float* __restrict__ bf,
                               float* __restrict__ x2, __half* __restrict__ h2)
{
    __shared__ float s_a[8], s_b[8];
    __shared__ float s_mu, s_rs;
    size_t row = blockIdx.x;
    int tid = threadIdx.x;
    float4 v  = ((const float4*)(x    + row * DIMV))[tid];
    float4 ov = ((const float4*)(oatt + row * DIMV))[tid];
    v.x += ov.x; v.y += ov.y; v.z += ov.z; v.w += ov.w;
    ((float4*)(x2 + row * DIMV))[tid] = v;

    float sum = v.x + v.y + v.z + v.w;
    float sq  = v.x*v.x + v.y*v.y + v.z*v.z + v.w*v.w;
    #pragma unroll
    for (int o = 16; o; o >>= 1) {
        sum += __shfl_xor_sync(0xffffffffu, sum, o);
        sq  += __shfl_xor_sync(0xffffffffu, sq,  o);
    }
    if ((tid & 31) == 0) { s_a[tid >> 5] = sum; s_b[tid >> 5] = sq; }
    __syncthreads();
    if (tid == 0) {
        float ts = 0.f, tq = 0.f;
        #pragma unroll
        for (int i = 0; i < 8; i++) { ts += s_a[i]; tq += s_b[i]; }
        float mu  = ts * (1.0f / DIMV);
        float var = tq * (1.0f / DIMV) - mu * mu;
        s_mu = mu; s_rs = rsqrtf(var + 1e-5f);
    }
    __syncthreads();
    float mu1 = s_mu, rs1 = s_rs;
    float4 g2v = ((const float4*)g2)[tid];
    float4 b2v = ((const float4*)b2)[tid];
    float4 t;
    t.x = (v.x - mu1) * rs1 * g2v.x + b2v.x;
    t.y = (v.y - mu1) * rs1 * g2v.y + b2v.y;
    t.z = (v.z - mu1) * rs1 * g2v.z + b2v.z;
    t.w = (v.w - mu1) * rs1 * g2v.w + b2v.w;

    float sum2 = t.x + t.y + t.z + t.w;
    float sq2  = t.x*t.x + t.y*t.y + t.z*t.z + t.w*t.w;
    #pragma unroll
    for (int o = 16; o; o >>= 1) {
        sum2 += __shfl_xor_sync(0xffffffffu, sum2, o);
        sq2  += __shfl_xor_sync(0xffffffffu, sq2,  o);
    }
    if ((tid & 31) == 0) { s_a[tid >> 5] = sum2; s_b[tid >> 5] = sq2; }
    __syncthreads();
    if (tid == 0) {
        float ts = 0.f, tq = 0.f;
        #pragma unroll
        for (int i = 0; i < 8; i++) { ts += s_a[i]; tq += s_b[i]; }
        float mu  = ts * (1.0f / DIMV);
        float var = tq * (1.0f / DIMV) - mu * mu;
        s_mu = mu; s_rs = rsqrtf(var + 1e-5f);
    }
    __syncthreads();
    float mu2 = s_mu, rs2 = s_rs;
    float4 gfv = ((const float4*)gf)[tid];
    float4 bfv = ((const float4*)bf)[tid];
    __half2 h0, h1;
    h0.x = __float2half_rn((t.x - mu2) * rs2 * gfv.x + bfv.x);
    h0.y = __float2half_rn((t.y - mu2) * rs2 * gfv.y + bfv.y);
    h1.x = __float2half_rn((t.z - mu2) * rs2 * gfv.z + bfv.z);
    h1.y = __float2half_rn((t.w - mu2) * rs2 * gfv.w + bfv.w);
    ((__half2*)(h2 + row * DIMV))[tid * 2 + 0] = h0;
    ((__half2*)(h2 + row * DIMV))[tid * 2 + 1] = h1;
}

// ---------------- fp16 GEMM: 4-stage cp.async, one barrier per kt ----------------
template<int ACT, int RES, int OUT16>
__global__ void __launch_bounds__(256) gemm_f16(
    const __half* __restrict__ A, const __half* __restrict__ Bt,
    const float* __restrict__ bias, const float* __restrict__ resid,
    void* __restrict__ Cout, int N, int K)
{
    extern __shared__ float sm[];
    const int tid  = threadIdx.x;
    const int lane = tid & 31;
    const int warp = tid >> 5;
    const int wm = warp >> 2;
    const int wn = warp & 3;
    const int m0 = blockIdx.y * BM;
    const int n0 = blockIdx.x * BN;
    const int KT = K / BKS16;

    const int lrow = tid >> 2;
    const int lk8  = (tid & 3) * 8;
    const int lk4  = (tid & 3) * 4;

    const __half* Asrc0 = A  + (size_t)(m0 + lrow)      * K + lk8;
    const __half* Asrc1 = A  + (size_t)(m0 + lrow + 64) * K + lk8;
    const __half* Bsrc0 = Bt + (size_t)(n0 + lrow)      * K + lk8;
    const __half* Bsrc1 = Bt + (size_t)(n0 + lrow + 64) * K + lk8;

    const uint32_t smb = smem_u32(sm);
    const uint32_t dA0 = smb + ((lrow)      * 20 + lk4) * 4;
    const uint32_t dA1 = smb + ((lrow + 64) * 20 + lk4) * 4;
    const uint32_t dB0 = dA0 + TILE_H * 4;
    const uint32_t dB1 = dA1 + TILE_H * 4;

    // ldmatrix lane offsets (bytes from tile base; row stride 80 B)
    const uint32_t aOff = (uint32_t)(wm * 64 + (lane & 15)) * 80 + ((lane >> 4) * 8) * 2;
    const uint32_t bOff = (uint32_t)(wn * 32 + (lane & 7) + ((lane >> 4) * 8)) * 80
                        + (((lane >> 3) & 1) * 8) * 2;

    // prologue: fill 3 of 4 stages
    #pragma unroll
    for (int s = 0; s < 3; s++) {
        uint32_t off = s * STAGE_H * 4;
        int k0 = s * BKS16;
        cp_async16(dA0 + off, Asrc0 + k0);
        cp_async16(dA1 + off, Asrc1 + k0);
        cp_async16(dB0 + off, Bsrc0 + k0);
        cp_async16(dB1 + off, Bsrc1 + k0);
        CP_COMMIT();
    }

    float acc[4][4][4] = {};
    const int gr = lane >> 2;
    const int tg = lane & 3;

    for (int kt = 0; kt < KT; kt++) {
        CP_WAIT2();
        __syncthreads();
        const uint32_t stage = smb + (kt & 3) * STAGE_H * 4;
        const uint32_t aBase = stage + aOff;
        const uint32_t bBase = stage + TILE_H * 4 + bOff;

        #pragma unroll
        for (int kc = 0; kc < 2; kc++) {
            uint32_t af[4][4], bf[4][2];
            #pragma unroll
            for (int mb = 0; mb < 4; mb++)
                ldsm_x4(aBase + mb * 1280 + kc * 32,
                        af[mb][0], af[mb][1], af[mb][2], af[mb][3]);
            #pragma unroll
            for (int p = 0; p < 2; p++)
                ldsm_x4(bBase + p * 1280 + kc * 32,
                        bf[2*p][0], bf[2*p][1], bf[2*p+1][0], bf[2*p+1][1]);
            #pragma unroll
            for (int mb = 0; mb < 4; mb++)
                #pragma unroll
                for (int nb = 0; nb < 4; nb++)
                    mma_f16(acc[mb][nb], af[mb], bf[nb]);
        }

        if (kt + 3 < KT) {
            uint32_t off = ((kt + 3) & 3) * STAGE_H * 4;
            int k0 = (kt + 3) * BKS16;
            cp_async16(dA0 + off, Asrc0 + k0);
            cp_async16(dA1 + off, Asrc1 + k0);
            cp_async16(dB0 + off, Bsrc0 + k0);
            cp_async16(dB1 + off, Bsrc1 + k0);
        }
        CP_COMMIT();
    }

    #pragma unroll
    for (int mb = 0; mb < 4; mb++) {
        int rlo = m0 + wm * 64 + mb * 16 + gr;
        #pragma unroll
        for (int nb = 0; nb < 4; nb++) {
            int col = n0 + wn * 32 + nb * 8 + tg * 2;
            float2 bi = *(const float2*)(bias + col);
            #pragma unroll
            for (int half_i = 0; half_i < 2; half_i++) {
                int row = rlo + half_i * 8;
                float v0 = acc[mb][nb][half_i * 2 + 0] + bi.x;
                float v1 = acc[mb][nb][half_i * 2 + 1] + bi.y;
                if (ACT) { v0 = gelu_exact(v0); v1 = gelu_exact(v1); }
                if (RES) {
                    float2 rv = *(const float2*)(resid + (size_t)row * N + col);
                    v0 += rv.x; v1 += rv.y;
                }
                if (OUT16) {
                    __half2 o2;
                    o2.x = __float2half_rn(v0);
                    o2.y = __float2half_rn(v1);
                    *(__half2*)((__half*)Cout + (size_t)row * N + col) = o2;
                } else {
                    float2 o2; o2.x = v0; o2.y = v1;
                    *(float2*)((float*)Cout + (size_t)row * N + col) = o2;
                }
            }
        }
    }
}

// ---------------- fp16 flash attention: q-tile 128, 8 warps ----------------
__global__ void __launch_bounds__(256) attn_kernel(
    const __half* __restrict__ QKV, float* __restrict__ O)
{
    extern __shared__ __half smh[];
    // layout: K[2][64][AT_PADH], V[2][64][AT_PADH]

    const int qt = blockIdx.x;            // 0..15 (128-row q tiles)
    const int bh = blockIdx.y;
    const int b  = bh >> 4;
    const int h  = bh & 15;
    const int tid  = threadIdx.x;
    const int lane = tid & 31;
    const int w    = tid >> 5;            // 0..7, owns q-rows w*16..+16
    const int gr   = lane >> 2;
    const int tg   = lane & 3;

    const __half* Qb = QKV + (size_t)b * SEQ * QKV_LD + h * HDIMV;
    const __half* Kb = Qb + 1024;
    const __half* Vb = Qb + 2048;

    const uint32_t smb = smem_u32(smh);
    const uint32_t KsB = smb;
    const uint32_t VsB = smb + 2 * AT_TILEH * 2;

    // ldmatrix lane offsets (row stride = AT_PADH*2 = 144 B)
    const uint32_t kOff = (uint32_t)((lane & 7) + ((lane >> 4) * 8)) * (AT_PADH * 2)
                        + (((lane >> 3) & 1) * 8) * 2;
    const uint32_t vOff = (uint32_t)((lane & 7) + (((lane >> 3) & 1) * 8)) * (AT_PADH * 2)
                        + ((lane >> 4) * 8) * 2;

    // ---- Q fragments straight from global (scaled by 1/8, exact in fp16) ----
    uint32_t qf[4][4];
    {
        const __half2 sc = __float2half2_rn(0.125f);
        const int r = qt * BQ + w * 16 + gr;
        #pragma unroll
        for (int kc = 0; kc < 4; kc++) {
            #pragma unroll
            for (int e = 0; e < 4; e++) {
                int rr = r + ((e & 1) ? 8 : 0);
                int dd = kc * 16 + ((e & 2) ? 8 : 0) + tg * 2;
                __half2 v = *(const __half2*)(Qb + (size_t)rr * QKV_LD + dd);
                v = __hmul2(v, sc);
                qf[kc][e] = *(uint32_t*)&v;
            }
        }
    }

    const int KTILES = 2 * qt + 2;        // k-tiles 0 .. 2qt+1 (64 rows each)

    // ---- prologue: load K/V tile 0 (512 cp.asyncs over 256 threads) ----
    #pragma unroll
    for (int j = 0; j < 2; j++) {
        int idx = j * 256 + tid;
        int r  = idx >> 3;
        int c8 = (idx & 7) * 8;
        uint32_t doff = (r * AT_PADH + c8) * 2;
        cp_async16(KsB + doff, Kb + (size_t)r * QKV_LD + c8);
        cp_async16(VsB + doff, Vb + (size_t)r * QKV_LD + c8);
    }
    CP_COMMIT();

    float oacc[8][4] = {};
    float rm[2] = { -3e38f, -3e38f };
    float rl[2] = { 0.f, 0.f };

    for (int kt = 0; kt < KTILES; kt++) {
        const int buf = kt & 1;
        if (kt + 1 < KTILES) {
            const int nbuf = (kt + 1) & 1;
            const size_t krow0 = (size_t)(kt + 1) * 64;
            #pragma unroll
            for (int j = 0; j < 2; j++) {
                int idx = j * 256 + tid;
                int r  = idx >> 3;
                int c8 = (idx & 7) * 8;
                uint32_t doff = (nbuf * AT_TILEH + r * AT_PADH + c8) * 2;
                cp_async16(KsB + doff, Kb + (krow0 + r) * QKV_LD + c8);
                cp_async16(VsB + doff, Vb + (krow0 + r) * QKV_LD + c8);
            }
            CP_COMMIT();
            CP_WAIT1();
        } else {
            CP_WAIT0();
        }
        __syncthreads();

        const uint32_t KtB = KsB + buf * AT_TILEH * 2 + kOff;
        const uint32_t VtB = VsB + buf * AT_TILEH * 2 + vOff;

        // ---- S = Q @ K^T (ldmatrix K B-frags) ----
        float s[8][4] = {};
        #pragma unroll
        for (int kc = 0; kc < 4; kc++) {
            uint32_t bf[8][2];
            #pragma unroll
            for (int p = 0; p < 4; p++)
                ldsm_x4(KtB + p * 16 * (AT_PADH * 2) + kc * 32,
                        bf[2*p][0], bf[2*p][1], bf[2*p+1][0], bf[2*p+1][1]);
            #pragma unroll
            for (int nb = 0; nb < 8; nb++)
                mma_f16(s[nb], qf[kc], bf[nb]);
        }

        // ---- causal mask on the two diagonal-straddling k-tiles ----
        if (kt >= 2 * qt) {
            const int grow = qt * BQ + w * 16 + gr;
            const int gcol0 = kt * 64;
            #pragma unroll
            for (int nb = 0; nb < 8; nb++)
                #pragma unroll
                for (int e = 0; e < 4; e++) {
                    int row = grow + (e >> 1) * 8;
                    int col = gcol0 + nb * 8 + tg * 2 + (e & 1);
                    if (col > row) s[nb][e] = -3e38f;
                }
        }

        // ---- online softmax (register stats, quad shuffle) ----
        float alpha[2];
        #pragma unroll
        for (int hh = 0; hh < 2; hh++) {
            float mloc = -3e38f;
            #pragma unroll
            for (int nb = 0; nb < 8; nb++) {
                mloc = fmaxf(mloc, s[nb][hh * 2 + 0]);
                mloc = fmaxf(mloc, s[nb][hh * 2 + 1]);
            }
            mloc = fmaxf(mloc, __shfl_xor_sync(0xffffffffu, mloc, 1));
            mloc = fmaxf(mloc, __shfl_xor_sync(0xffffffffu, mloc, 2));
            float mnew = fmaxf(rm[hh], mloc);
            alpha[hh] = __expf(rm[hh] - mnew);
            float suml = 0.f;
            #pragma unroll
            for (int nb = 0; nb < 8; nb++) {
                float p0 = __expf(s[nb][hh * 2 + 0] - mnew);
                float p1 = __expf(s[nb][hh * 2 + 1] - mnew);
                s[nb][hh * 2 + 0] = p0;
                s[nb][hh * 2 + 1] = p1;
                suml += p0 + p1;
            }
            suml += __shfl_xor_sync(0xffffffffu, suml, 1);
            suml += __shfl_xor_sync(0xffffffffu, suml, 2);
            rl[hh] = rl[hh] * alpha[hh] + suml;
            rm[hh] = mnew;
        }

        #pragma unroll
        for (int nb = 0; nb < 8; nb++) {
            oacc[nb][0] *= alpha[0]; oacc[nb][1] *= alpha[0];
            oacc[nb][2] *= alpha[1]; oacc[nb][3] *= alpha[1];
        }

        // ---- O += P @ V : A-frags from S registers, V via ldmatrix.trans ----
        #pragma unroll
        for (int kc = 0; kc < 4; kc++) {
            uint32_t af[4];
            {
                __half2 a0 = __floats2half2_rn(s[2*kc][0],   s[2*kc][1]);
                __half2 a1 = __floats2half2_rn(s[2*kc][2],   s[2*kc][3]);
                __half2 a2 = __floats2half2_rn(s[2*kc+1][0], s[2*kc+1][1]);
                __half2 a3 = __floats2half2_rn(s[2*kc+1][2], s[2*kc+1][3]);
                af[0] = *(uint32_t*)&a0; af[1] = *(uint32_t*)&a1;
                af[2] = *(uint32_t*)&a2; af[3] = *(uint32_t*)&a3;
            }
            uint32_t bf[8][2];
            #pragma unroll
            for (int p = 0; p < 4; p++)
                ldsm_x4_t(VtB + kc * 16 * (AT_PADH * 2) + p * 32,
                          bf[2*p][0], bf[2*p][1], bf[2*p+1][0], bf[2*p+1][1]);
            #pragma unroll
            for (int nb = 0; nb < 8; nb++)
                mma_f16(oacc[nb], af, bf[nb]);
        }
        __syncthreads();   // protect K/V buffers before next iteration's loads
    }

    // ---- normalize + write (concat-head layout) ----
    float linv0 = 1.0f / rl[0];
    float linv1 = 1.0f / rl[1];
    #pragma unroll
    for (int hh = 0; hh < 2; hh++) {
        size_t row = (size_t)b * SEQ + (size_t)(qt * BQ + w * 16 + gr + hh * 8);
        float linv = hh ? linv1 : linv0;
        #pragma unroll
        for (int nb = 0; nb < 8; nb++) {
            float2 o2;
            o2.x = oacc[nb][hh * 2 + 0] * linv;
            o2.y = oacc[nb][hh * 2 + 1] * linv;
            *(float2*)(O + row * DIMV + h * HDIMV + nb * 8 + tg * 2) = o2;
        }
    }
}

extern "C" void kernel_launch(void* const* d_in, const int* in_sizes, int n_in,
                              void* d_out, int out_size)
{
    const float* x    = (const float*)d_in[0];
    const float* ln1g = (const float*)d_in[1];
    const float* ln1b = (const float*)d_in[2];
    const float* Wq   = (const float*)d_in[3];
    const float* bq   = (const float*)d_in[4];
    const float* Wk   = (const float*)d_in[5];
    const float* bk   = (const float*)d_in[6];
    const float* Wv   = (const float*)d_in[7];
    const float* bv   = (const float*)d_in[8];
    const float* ln2g = (const float*)d_in[9];
    const float* ln2b = (const float*)d_in[10];
    const float* fclg = (const float*)d_in[11];
    const float* fclb = (const float*)d_in[12];
    const float* W1   = (const float*)d_in[13];
    const float* b1   = (const float*)d_in[14];
    const float* W2   = (const float*)d_in[15];
    const float* b2   = (const float*)d_in[16];
    float* out = (float*)d_out;

    float *p_o, *p_x2, *p_bqkv;
    __half *p_h, *p_qkv, *p_h2, *p_mid, *p_wt, *p_w1t, *p_w2t;
    cudaGetSymbolAddress((void**)&p_h,    g_h);
    cudaGetSymbolAddress((void**)&p_qkv,  g_qkv);
    cudaGetSymbolAddress((void**)&p_o,    g_o);
    cudaGetSymbolAddress((void**)&p_x2,   g_x2);
    cudaGetSymbolAddress((void**)&p_h2,   g_h2);
    cudaGetSymbolAddress((void**)&p_mid,  g_mid);
    cudaGetSymbolAddress((void**)&p_wt,   g_wt);
    cudaGetSymbolAddress((void**)&p_w1t,  g_w1t);
    cudaGetSymbolAddress((void**)&p_w2t,  g_w2t);
    cudaGetSymbolAddress((void**)&p_bqkv, g_bqkv);

    cudaFuncSetAttribute(attn_kernel, cudaFuncAttributeMaxDynamicSharedMemorySize, ATTN_SMEM_B);
    cudaFuncSetAttribute(gemm_f16<0,0,1>, cudaFuncAttributeMaxDynamicSharedMemorySize, GEMM_SMEM_BYTES);
    cudaFuncSetAttribute(gemm_f16<1,0,1>, cudaFuncAttributeMaxDynamicSharedMemorySize, GEMM_SMEM_BYTES);
    cudaFuncSetAttribute(gemm_f16<1,1,0>, cudaFuncAttributeMaxDynamicSharedMemorySize, GEMM_SMEM_BYTES);

    transpose_qkv_kernel<<<dim3(2, 32, 48), dim3(32, 8)>>>(Wq, Wk, Wv, p_wt);
    transpose_kernel_h16<<<dim3(HIDV / 32, DIMV / 32), dim3(32, 8)>>>(W1, p_w1t, DIMV, HIDV);
    transpose_kernel_h16<<<dim3(DIMV / 32, HIDV / 32), dim3(32, 8)>>>(W2, p_w2t, HIDV, DIMV);
    pack_bias_kernel<<<QKV_LD / 256, 256>>>(bq, bk, bv, p_bqkv);
    ln_kernel<<<NTOK, 256>>>(x, ln1g, ln1b, p_h);
    gemm_f16<0,0,1><<<dim3(QKV_LD / BN, NTOK / BM), 256, GEMM_SMEM_BYTES>>>(
        p_h, p_wt, p_bqkv, nullptr, p_qkv, QKV_LD, DIMV);
    attn_kernel<<<dim3(SEQ / BQ, 64), 256, ATTN_SMEM_B>>>(p_qkv, p_o);
    add_dln_kernel<<<NTOK, 256>>>(x, p_o, ln2g, ln2b, fclg, fclb, p_x2, p_h2);
    gemm_f16<1,0,1><<<dim3(HIDV / BN, NTOK / BM), 256, GEMM_SMEM_BYTES>>>(
        p_h2, p_w1t, b1, nullptr, p_mid, HIDV, DIMV);
    gemm_f16<1,1,0><<<dim3(DIMV / BN, NTOK / BM), 256, GEMM_SMEM_BYTES>>>(
        p_mid, p_w2t, b2, p_x2, out, DIMV, HIDV);
}

// round 13
// speedup vs baseline: 1.1721x; 1.0529x over previous
#include <cuda_runtime.h>
#include <cuda_fp16.h>
#include <cstdint>
#include <cstddef>

// Problem dims
#define DIMV   1024
#define HIDV   4096
#define SEQ    2048
#define NHEAD  16
#define HDIMV  64
#define NTOK   8192          // B * S
#define QKV_LD 3072          // fused QKV row stride

// GEMM tiling (fp16 mma m16n8k16): 128x256 tile, 512 threads, 32 K/stage, 4 stages
#define BM 128
#define BN 256
#define BKS16 32
#define TILE_A 2560          // b32: 128 rows * 20
#define TILE_B 5120          // b32: 256 rows * 20
#define STAGE_W (TILE_A + TILE_B)   // 7680 b32 per stage
#define NSTAGE 4
#define GEMM_SMEM_BYTES (NSTAGE * STAGE_W * 4)   // 122880

// attention: q-tile 128, k-tile 64, fp16 smem tiles (K/V double buffered)
#define AT_PADH 72
#define AT_TILEH (64 * AT_PADH)
#define ATTN_SMEM_B (4 * AT_TILEH * 2)     // 36864 B
#define BQ 128

// ---------------- static scratch ----------------
__device__ __half g_h  [(size_t)NTOK * DIMV];
__device__ __half g_qkv[(size_t)NTOK * QKV_LD];
__device__ float  g_o  [(size_t)NTOK * DIMV];
__device__ float  g_x2 [(size_t)NTOK * DIMV];
__device__ __half g_h2 [(size_t)NTOK * DIMV];
__device__ __half g_mid[(size_t)NTOK * HIDV];
__device__ __half g_wt [(size_t)QKV_LD * DIMV];
__device__ __half g_w1t[(size_t)HIDV * DIMV];
__device__ __half g_w2t[(size_t)DIMV * HIDV];
__device__ float  g_bqkv[QKV_LD];

// ---------------- helpers ----------------
__device__ __forceinline__ uint32_t smem_u32(const void* p) {
    uint32_t a;
    asm("{ .reg .u64 t; cvta.to.shared.u64 t, %1; cvt.u32.u64 %0, t; }" : "=r"(a) : "l"(p));
    return a;
}

__device__ __forceinline__ float gelu_exact(float x) {
    return 0.5f * x * (1.0f + erff(x * 0.70710678118654752f));
}

__device__ __forceinline__ void cp_async16(uint32_t dst, const void* src) {
    asm volatile("cp.async.cg.shared.global [%0], [%1], 16;" :: "r"(dst), "l"(src));
}
#define CP_COMMIT() asm volatile("cp.async.commit_group;" ::: "memory")
#define CP_WAIT2()  asm volatile("cp.async.wait_group 2;" ::: "memory")
#define CP_WAIT1()  asm volatile("cp.async.wait_group 1;" ::: "memory")
#define CP_WAIT0()  asm volatile("cp.async.wait_group 0;" ::: "memory")

__device__ __forceinline__ void mma_f16(float* c, const uint32_t* a, const uint32_t* b) {
    asm volatile(
        "mma.sync.aligned.m16n8k16.row.col.f32.f16.f16.f32 "
        "{%0,%1,%2,%3}, {%4,%5,%6,%7}, {%8,%9}, {%0,%1,%2,%3};"
        : "+f"(c[0]), "+f"(c[1]), "+f"(c[2]), "+f"(c[3])
        : "r"(a[0]), "r"(a[1]), "r"(a[2]), "r"(a[3]), "r"(b[0]), "r"(b[1]));
}

__device__ __forceinline__ void ldsm_x4(uint32_t addr, uint32_t& r0, uint32_t& r1,
                                        uint32_t& r2, uint32_t& r3) {
    asm volatile("ldmatrix.sync.aligned.m8n8.x4.shared.b16 {%0,%1,%2,%3}, [%4];"
        : "=r"(r0), "=r"(r1), "=r"(r2), "=r"(r3) : "r"(addr));
}

__device__ __forceinline__ void ldsm_x4_t(uint32_t addr, uint32_t& r0, uint32_t& r1,
                                          uint32_t& r2, uint32_t& r3) {
    asm volatile("ldmatrix.sync.aligned.m8n8.x4.trans.shared.b16 {%0,%1,%2,%3}, [%4];"
        : "=r"(r0), "=r"(r1), "=r"(r2), "=r"(r3) : "r"(addr));
}

// ---------------- weight transposes (fp16 output) ----------------
__global__ void transpose_kernel_h16(const float* __restrict__ src, __half* __restrict__ dst,
                                     int R, int C)
{
    __shared__ float t[32][33];
    int c0 = blockIdx.x * 32, r0 = blockIdx.y * 32;
    int tx = threadIdx.x, ty = threadIdx.y;
    #pragma unroll
    for (int i = 0; i < 32; i += 8)
        t[ty + i][tx] = src[(size_t)(r0 + ty + i) * C + c0 + tx];
    __syncthreads();
    #pragma unroll
    for (int i = 0; i < 32; i += 8)
        dst[(size_t)(c0 + ty + i) * R + r0 + tx] = __float2half_rn(t[tx][ty + i]);
}

__global__ void transpose_qkv_kernel(const float* __restrict__ Wq, const float* __restrict__ Wk,
                                     const float* __restrict__ Wv, __half* __restrict__ dst)
{
    __shared__ float t[32][33];
    int s = blockIdx.z, w = s >> 4, h = s & 15;
    const float* W = ((w == 0) ? Wq : (w == 1) ? Wk : Wv) + (size_t)h * DIMV * HDIMV;
    __half* D = dst + (size_t)(w * 1024 + h * 64) * DIMV;
    int c0 = blockIdx.x * 32, r0 = blockIdx.y * 32;
    int tx = threadIdx.x, ty = threadIdx.y;
    #pragma unroll
    for (int i = 0; i < 32; i += 8)
        t[ty + i][tx] = W[(size_t)(r0 + ty + i) * HDIMV + c0 + tx];
    __syncthreads();
    #pragma unroll
    for (int i = 0; i < 32; i += 8)
        D[(size_t)(c0 + ty + i) * DIMV + r0 + tx] = __float2half_rn(t[tx][ty + i]);
}

__global__ void pack_bias_kernel(const float* __restrict__ bq, const float* __restrict__ bk,
                                 const float* __restrict__ bv, float* __restrict__ dst)
{
    int i = blockIdx.x * 256 + threadIdx.x;
    float v = (i < 1024) ? bq[i] : (i < 2048) ? bk[i - 1024] : bv[i - 2048];
    dst[i] = v;
}

// ---------------- LayerNorm (fp16 output) ----------------
__global__ void ln_kernel(const float* __restrict__ x, const float* __restrict__ g,
                          const float* __restrict__ b, __half* __restrict__ y)
{
    __shared__ float s_a[8], s_b[8];
    __shared__ float s_mu, s_rs;
    size_t row = blockIdx.x;
    int tid = threadIdx.x;
    float4 v = ((const float4*)(x + row * DIMV))[tid];
    float sum = v.x + v.y + v.z + v.w;
    float sq  = v.x*v.x + v.y*v.y + v.z*v.z + v.w*v.w;
    #pragma unroll
    for (int o = 16; o; o >>= 1) {
        sum += __shfl_xor_sync(0xffffffffu, sum, o);
        sq  += __shfl_xor_sync(0xffffffffu, sq,  o);
    }
    if ((tid & 31) == 0) { s_a[tid >> 5] = sum; s_b[tid >> 5] = sq; }
    __syncthreads();
    if (tid == 0) {
        float ts = 0.f, tq = 0.f;
        #pragma unroll
        for (int i = 0; i < 8; i++) { ts += s_a[i]; tq += s_b[i]; }
        float mu  = ts * (1.0f / DIMV);
        float var = tq * (1.0f / DIMV) - mu * mu;
        s_mu = mu; s_rs = rsqrtf(var + 1e-5f);
    }
    __syncthreads();
    float mu = s_mu, rs = s_rs;
    float4 gv = ((const float4*)g)[tid];
    float4 bv = ((const float4*)b)[tid];
    __half2 h0, h1;
    h0.x = __float2half_rn((v.x - mu) * rs * gv.x + bv.x);
    h0.y = __float2half_rn((v.y - mu) * rs * gv.y + bv.y);
    h1.x = __float2half_rn((v.z - mu) * rs * gv.z + bv.z);
    h1.y = __float2half_rn((v.w - mu) * rs * gv.w + bv.w);
    ((__half2*)(y + row * DIMV))[tid * 2 + 0] = h0;
    ((__half2*)(y + row * DIMV))[tid * 2 + 1] = h1;
}

// ---------------- residual add + LN(ln2) + LN(fcln), h2 out fp16 ----------------
__global__ void add_dln_kernel(const float* __restrict__ x, const float* __restrict__ oatt,
                               const float* __restrict__ g2, const float* __restrict__ b2,
                               const float* __restrict__ gf, const float* __restrict__ bf,
                               float* __restrict__ x2, __half* __restrict__ h2)
{
    __shared__ float s_a[8], s_b[8];
    __shared__ float s_mu, s_rs;
    size_t row = blockIdx.x;
    int tid = threadIdx.x;
    float4 v  = ((const float4*)(x    + row * DIMV))[tid];
    float4 ov = ((const float4*)(oatt + row * DIMV))[tid];
    v.x += ov.x; v.y += ov.y; v.z += ov.z; v.w += ov.w;
    ((float4*)(x2 + row * DIMV))[tid] = v;

    float sum = v.x + v.y + v.z + v.w;
    float sq  = v.x*v.x + v.y*v.y + v.z*v.z + v.w*v.w;
    #pragma unroll
    for (int o = 16; o; o >>= 1) {
        sum += __shfl_xor_sync(0xffffffffu, sum, o);
        sq  += __shfl_xor_sync(0xffffffffu, sq,  o);
    }
    if ((tid & 31) == 0) { s_a[tid >> 5] = sum; s_b[tid >> 5] = sq; }
    __syncthreads();
    if (tid == 0) {
        float ts = 0.f, tq = 0.f;
        #pragma unroll
        for (int i = 0; i < 8; i++) { ts += s_a[i]; tq += s_b[i]; }
        float mu  = ts * (1.0f / DIMV);
        float var = tq * (1.0f / DIMV) - mu * mu;
        s_mu = mu; s_rs = rsqrtf(var + 1e-5f);
    }
    __syncthreads();
    float mu1 = s_mu, rs1 = s_rs;
    float4 g2v = ((const float4*)g2)[tid];
    float4 b2v = ((const float4*)b2)[tid];
    float4 t;
    t.x = (v.x - mu1) * rs1 * g2v.x + b2v.x;
    t.y = (v.y - mu1) * rs1 * g2v.y + b2v.y;
    t.z = (v.z - mu1) * rs1 * g2v.z + b2v.z;
    t.w = (v.w - mu1) * rs1 * g2v.w + b2v.w;

    float sum2 = t.x + t.y + t.z + t.w;
    float sq2  = t.x*t.x + t.y*t.y + t.z*t.z + t.w*t.w;
    #pragma unroll
    for (int o = 16; o; o >>= 1) {
        sum2 += __shfl_xor_sync(0xffffffffu, sum2, o);
        sq2  += __shfl_xor_sync(0xffffffffu, sq2,  o);
    }
    if ((tid & 31) == 0) { s_a[tid >> 5] = sum2; s_b[tid >> 5] = sq2; }
    __syncthreads();
    if (tid == 0) {
        float ts = 0.f, tq = 0.f;
        #pragma unroll
        for (int i = 0; i < 8; i++) { ts += s_a[i]; tq += s_b[i]; }
        float mu  = ts * (1.0f / DIMV);
        float var = tq * (1.0f / DIMV) - mu * mu;
        s_mu = mu; s_rs = rsqrtf(var + 1e-5f);
    }
    __syncthreads();
    float mu2 = s_mu, rs2 = s_rs;
    float4 gfv = ((const float4*)gf)[tid];
    float4 bfv = ((const float4*)bf)[tid];
    __half2 h0, h1;
    h0.x = __float2half_rn((t.x - mu2) * rs2 * gfv.x + bfv.x);
    h0.y = __float2half_rn((t.y - mu2) * rs2 * gfv.y + bfv.y);
    h1.x = __float2half_rn((t.z - mu2) * rs2 * gfv.z + bfv.z);
    h1.y = __float2half_rn((t.w - mu2) * rs2 * gfv.w + bfv.w);
    ((__half2*)(h2 + row * DIMV))[tid * 2 + 0] = h0;
    ((__half2*)(h2 + row * DIMV))[tid * 2 + 1] = h1;
}

// ---------------- fp16 GEMM: 128x256 tile, 512 threads, 4-stage cp.async ----------------
// 16 warps: wm = warp>>2 (m strip of 32), wn = warp&3 (n strip of 64)
template<int ACT, int RES, int OUT16>
__global__ void __launch_bounds__(512) gemm_f16(
    const __half* __restrict__ A, const __half* __restrict__ Bt,
    const float* __restrict__ bias, const float* __restrict__ resid,
    void* __restrict__ Cout, int N, int K)
{
    extern __shared__ float sm[];
    const int tid  = threadIdx.x;
    const int lane = tid & 31;
    const int warp = tid >> 5;
    const int wm = warp >> 2;       // 0..3
    const int wn = warp & 3;        // 0..3
    const int m0 = blockIdx.y * BM;
    const int n0 = blockIdx.x * BN;
    const int KT = K / BKS16;

    // loader mapping: thread t does A chunk t, B chunks t and t+512
    const int lrow = tid >> 2;          // 0..127
    const int lk8  = (tid & 3) * 8;
    const int lk4  = (tid & 3) * 4;

    const __half* Asrc  = A  + (size_t)(m0 + lrow)       * K + lk8;
    const __half* Bsrc0 = Bt + (size_t)(n0 + lrow)       * K + lk8;
    const __half* Bsrc1 = Bt + (size_t)(n0 + lrow + 128) * K + lk8;

    const uint32_t smb = smem_u32(sm);
    const uint32_t dA  = smb + (lrow * 20 + lk4) * 4;
    const uint32_t dB0 = smb + TILE_A * 4 + (lrow * 20 + lk4) * 4;
    const uint32_t dB1 = dB0 + 128 * 20 * 4;

    // ldmatrix lane offsets (bytes from tile base; row stride 80 B)
    const uint32_t aOff = (uint32_t)(wm * 32 + (lane & 15)) * 80 + ((lane >> 4) * 8) * 2;
    const uint32_t bOff = (uint32_t)(wn * 64 + (lane & 7) + ((lane >> 4) * 8)) * 80
                        + (((lane >> 3) & 1) * 8) * 2;

    // prologue: fill 3 of 4 stages
    #pragma unroll
    for (int s = 0; s < 3; s++) {
        uint32_t off = s * STAGE_W * 4;
        int k0 = s * BKS16;
        cp_async16(dA  + off, Asrc  + k0);
        cp_async16(dB0 + off, Bsrc0 + k0);
        cp_async16(dB1 + off, Bsrc1 + k0);
        CP_COMMIT();
    }

    float acc[2][8][4] = {};
    const int gr = lane >> 2;
    const int tg = lane & 3;

    for (int kt = 0; kt < KT; kt++) {
        CP_WAIT2();
        __syncthreads();
        const uint32_t stage = smb + (kt & 3) * STAGE_W * 4;
        const uint32_t aBase = stage + aOff;
        const uint32_t bBase = stage + TILE_A * 4 + bOff;

        #pragma unroll
        for (int kc = 0; kc < 2; kc++) {
            uint32_t af[2][4], bf[8][2];
            #pragma unroll
            for (int mb = 0; mb < 2; mb++)
                ldsm_x4(aBase + mb * 1280 + kc * 32,
                        af[mb][0], af[mb][1], af[mb][2], af[mb][3]);
            #pragma unroll
            for (int p = 0; p < 4; p++)
                ldsm_x4(bBase + p * 1280 + kc * 32,
                        bf[2*p][0], bf[2*p][1], bf[2*p+1][0], bf[2*p+1][1]);
            #pragma unroll
            for (int mb = 0; mb < 2; mb++)
                #pragma unroll
                for (int nb = 0; nb < 8; nb++)
                    mma_f16(acc[mb][nb], af[mb], bf[nb]);
        }

        if (kt + 3 < KT) {
            uint32_t off = ((kt + 3) & 3) * STAGE_W * 4;
            int k0 = (kt + 3) * BKS16;
            cp_async16(dA  + off, Asrc  + k0);
            cp_async16(dB0 + off, Bsrc0 + k0);
            cp_async16(dB1 + off, Bsrc1 + k0);
        }
        CP_COMMIT();
    }

    #pragma unroll
    for (int mb = 0; mb < 2; mb++) {
        int rlo = m0 + wm * 32 + mb * 16 + gr;
        #pragma unroll
        for (int nb = 0; nb < 8; nb++) {
            int col = n0 + wn * 64 + nb * 8 + tg * 2;
            float2 bi = *(const float2*)(bias + col);
            #pragma unroll
            for (int half_i = 0; half_i < 2; half_i++) {
                int row = rlo + half_i * 8;
                float v0 = acc[mb][nb][half_i * 2 + 0] + bi.x;
                float v1 = acc[mb][nb][half_i * 2 + 1] + bi.y;
                if (ACT) { v0 = gelu_exact(v0); v1 = gelu_exact(v1); }
                if (RES) {
                    float2 rv = *(const float2*)(resid + (size_t)row * N + col);
                    v0 += rv.x; v1 += rv.y;
                }
                if (OUT16) {
                    __half2 o2;
                    o2.x = __float2half_rn(v0);
                    o2.y = __float2half_rn(v1);
                    *(__half2*)((__half*)Cout + (size_t)row * N + col) = o2;
                } else {
                    float2 o2; o2.x = v0; o2.y = v1;
                    *(float2*)((float*)Cout + (size_t)row * N + col) = o2;
                }
            }
        }
    }
}

// ---------------- fp16 flash attention: q-tile 128, 8 warps (unchanged R12) ----------------
__global__ void __launch_bounds__(256) attn_kernel(
    const __half* __restrict__ QKV, float* __restrict__ O)
{
    extern __shared__ __half smh[];

    const int qt = blockIdx.x;
    const int bh = blockIdx.y;
    const int b  = bh >> 4;
    const int h  = bh & 15;
    const int tid  = threadIdx.x;
    const int lane = tid & 31;
    const int w    = tid >> 5;
    const int gr   = lane >> 2;
    const int tg   = lane & 3;

    const __half* Qb = QKV + (size_t)b * SEQ * QKV_LD + h * HDIMV;
    const __half* Kb = Qb + 1024;
    const __half* Vb = Qb + 2048;

    const uint32_t smb = smem_u32(smh);
    const uint32_t KsB = smb;
    const uint32_t VsB = smb + 2 * AT_TILEH * 2;

    const uint32_t kOff = (uint32_t)((lane & 7) + ((lane >> 4) * 8)) * (AT_PADH * 2)
                        + (((lane >> 3) & 1) * 8) * 2;
    const uint32_t vOff = (uint32_t)((lane & 7) + (((lane >> 3) & 1) * 8)) * (AT_PADH * 2)
                        + ((lane >> 4) * 8) * 2;

    uint32_t qf[4][4];
    {
        const __half2 sc = __float2half2_rn(0.125f);
        const int r = qt * BQ + w * 16 + gr;
        #pragma unroll
        for (int kc = 0; kc < 4; kc++) {
            #pragma unroll
            for (int e = 0; e < 4; e++) {
                int rr = r + ((e & 1) ? 8 : 0);
                int dd = kc * 16 + ((e & 2) ? 8 : 0) + tg * 2;
                __half2 v = *(const __half2*)(Qb + (size_t)rr * QKV_LD + dd);
                v = __hmul2(v, sc);
                qf[kc][e] = *(uint32_t*)&v;
            }
        }
    }

    const int KTILES = 2 * qt + 2;

    #pragma unroll
    for (int j = 0; j < 2; j++) {
        int idx = j * 256 + tid;
        int r  = idx >> 3;
        int c8 = (idx & 7) * 8;
        uint32_t doff = (r * AT_PADH + c8) * 2;
        cp_async16(KsB + doff, Kb + (size_t)r * QKV_LD + c8);
        cp_async16(VsB + doff, Vb + (size_t)r * QKV_LD + c8);
    }
    CP_COMMIT();

    float oacc[8][4] = {};
    float rm[2] = { -3e38f, -3e38f };
    float rl[2] = { 0.f, 0.f };

    for (int kt = 0; kt < KTILES; kt++) {
        const int buf = kt & 1;
        if (kt + 1 < KTILES) {
            const int nbuf = (kt + 1) & 1;
            const size_t krow0 = (size_t)(kt + 1) * 64;
            #pragma unroll
            for (int j = 0; j < 2; j++) {
                int idx = j * 256 + tid;
                int r  = idx >> 3;
                int c8 = (idx & 7) * 8;
                uint32_t doff = (nbuf * AT_TILEH + r * AT_PADH + c8) * 2;
                cp_async16(KsB + doff, Kb + (krow0 + r) * QKV_LD + c8);
                cp_async16(VsB + doff, Vb + (krow0 + r) * QKV_LD + c8);
            }
            CP_COMMIT();
            CP_WAIT1();
        } else {
            CP_WAIT0();
        }
        __syncthreads();

        const uint32_t KtB = KsB + buf * AT_TILEH * 2 + kOff;
        const uint32_t VtB = VsB + buf * AT_TILEH * 2 + vOff;

        float s[8][4] = {};
        #pragma unroll
        for (int kc = 0; kc < 4; kc++) {
            uint32_t bf[8][2];
            #pragma unroll
            for (int p = 0; p < 4; p++)
                ldsm_x4(KtB + p * 16 * (AT_PADH * 2) + kc * 32,
                        bf[2*p][0], bf[2*p][1], bf[2*p+1][0], bf[2*p+1][1]);
            #pragma unroll
            for (int nb = 0; nb < 8; nb++)
                mma_f16(s[nb], qf[kc], bf[nb]);
        }

        if (kt >= 2 * qt) {
            const int grow = qt * BQ + w * 16 + gr;
            const int gcol0 = kt * 64;
            #pragma unroll
            for (int nb = 0; nb < 8; nb++)
                #pragma unroll
                for (int e = 0; e < 4; e++) {
                    int row = grow + (e >> 1) * 8;
                    int col = gcol0 + nb * 8 + tg * 2 + (e & 1);
                    if (col > row) s[nb][e] = -3e38f;
                }
        }

        float alpha[2];
        #pragma unroll
        for (int hh = 0; hh < 2; hh++) {
            float mloc = -3e38f;
            #pragma unroll
            for (int nb = 0; nb < 8; nb++) {
                mloc = fmaxf(mloc, s[nb][hh * 2 + 0]);
                mloc = fmaxf(mloc, s[nb][hh * 2 + 1]);
            }
            mloc = fmaxf(mloc, __shfl_xor_sync(0xffffffffu, mloc, 1));
            mloc = fmaxf(mloc, __shfl_xor_sync(0xffffffffu, mloc, 2));
            float mnew = fmaxf(rm[hh], mloc);
            alpha[hh] = __expf(rm[hh] - mnew);
            float suml = 0.f;
            #pragma unroll
            for (int nb = 0; nb < 8; nb++) {
                float p0 = __expf(s[nb][hh * 2 + 0] - mnew);
                float p1 = __expf(s[nb][hh * 2 + 1] - mnew);
                s[nb][hh * 2 + 0] = p0;
                s[nb][hh * 2 + 1] = p1;
                suml += p0 + p1;
            }
            suml += __shfl_xor_sync(0xffffffffu, suml, 1);
            suml += __shfl_xor_sync(0xffffffffu, suml, 2);
            rl[hh] = rl[hh] * alpha[hh] + suml;
            rm[hh] = mnew;
        }

        #pragma unroll
        for (int nb = 0; nb < 8; nb++) {
            oacc[nb][0] *= alpha[0]; oacc[nb][1] *= alpha[0];
            oacc[nb][2] *= alpha[1]; oacc[nb][3] *= alpha[1];
        }

        #pragma unroll
        for (int kc = 0; kc < 4; kc++) {
            uint32_t af[4];
            {
                __half2 a0 = __floats2half2_rn(s[2*kc][0],   s[2*kc][1]);
                __half2 a1 = __floats2half2_rn(s[2*kc][2],   s[2*kc][3]);
                __half2 a2 = __floats2half2_rn(s[2*kc+1][0], s[2*kc+1][1]);
                __half2 a3 = __floats2half2_rn(s[2*kc+1][2], s[2*kc+1][3]);
                af[0] = *(uint32_t*)&a0; af[1] = *(uint32_t*)&a1;
                af[2] = *(uint32_t*)&a2; af[3] = *(uint32_t*)&a3;
            }
            uint32_t bf[8][2];
            #pragma unroll
            for (int p = 0; p < 4; p++)
                ldsm_x4_t(VtB + kc * 16 * (AT_PADH * 2) + p * 32,
                          bf[2*p][0], bf[2*p][1], bf[2*p+1][0], bf[2*p+1][1]);
            #pragma unroll
            for (int nb = 0; nb < 8; nb++)
                mma_f16(oacc[nb], af, bf[nb]);
        }
        __syncthreads();
    }

    float linv0 = 1.0f / rl[0];
    float linv1 = 1.0f / rl[1];
    #pragma unroll
    for (int hh = 0; hh < 2; hh++) {
        size_t row = (size_t)b * SEQ + (size_t)(qt * BQ + w * 16 + gr + hh * 8);
        float linv = hh ? linv1 : linv0;
        #pragma unroll
        for (int nb = 0; nb < 8; nb++) {
            float2 o2;
            o2.x = oacc[nb][hh * 2 + 0] * linv;
            o2.y = oacc[nb][hh * 2 + 1] * linv;
            *(float2*)(O + row * DIMV + h * HDIMV + nb * 8 + tg * 2) = o2;
        }
    }
}

extern "C" void kernel_launch(void* const* d_in, const int* in_sizes, int n_in,
                              void* d_out, int out_size)
{
    const float* x    = (const float*)d_in[0];
    const float* ln1g = (const float*)d_in[1];
    const float* ln1b = (const float*)d_in[2];
    const float* Wq   = (const float*)d_in[3];
    const float* bq   = (const float*)d_in[4];
    const float* Wk   = (const float*)d_in[5];
    const float* bk   = (const float*)d_in[6];
    const float* Wv   = (const float*)d_in[7];
    const float* bv   = (const float*)d_in[8];
    const float* ln2g = (const float*)d_in[9];
    const float* ln2b = (const float*)d_in[10];
    const float* fclg = (const float*)d_in[11];
    const float* fclb = (const float*)d_in[12];
    const float* W1   = (const float*)d_in[13];
    const float* b1   = (const float*)d_in[14];
    const float* W2   = (const float*)d_in[15];
    const float* b2   = (const float*)d_in[16];
    float* out = (float*)d_out;

    float *p_o, *p_x2, *p_bqkv;
    __half *p_h, *p_qkv, *p_h2, *p_mid, *p_wt, *p_w1t, *p_w2t;
    cudaGetSymbolAddress((void**)&p_h,    g_h);
    cudaGetSymbolAddress((void**)&p_qkv,  g_qkv);
    cudaGetSymbolAddress((void**)&p_o,    g_o);
    cudaGetSymbolAddress((void**)&p_x2,   g_x2);
    cudaGetSymbolAddress((void**)&p_h2,   g_h2);
    cudaGetSymbolAddress((void**)&p_mid,  g_mid);
    cudaGetSymbolAddress((void**)&p_wt,   g_wt);
    cudaGetSymbolAddress((void**)&p_w1t,  g_w1t);
    cudaGetSymbolAddress((void**)&p_w2t,  g_w2t);
    cudaGetSymbolAddress((void**)&p_bqkv, g_bqkv);

    cudaFuncSetAttribute(attn_kernel, cudaFuncAttributeMaxDynamicSharedMemorySize, ATTN_SMEM_B);
    cudaFuncSetAttribute(gemm_f16<0,0,1>, cudaFuncAttributeMaxDynamicSharedMemorySize, GEMM_SMEM_BYTES);
    cudaFuncSetAttribute(gemm_f16<1,0,1>, cudaFuncAttributeMaxDynamicSharedMemorySize, GEMM_SMEM_BYTES);
    cudaFuncSetAttribute(gemm_f16<1,1,0>, cudaFuncAttributeMaxDynamicSharedMemorySize, GEMM_SMEM_BYTES);

    // lazy-created side streams/events for weight-prep overlap (host objects only)
    static cudaStream_t sA = nullptr, sB = nullptr;
    static cudaEvent_t  evF = nullptr, evA = nullptr, evB = nullptr;
    if (sA == nullptr) {
        cudaStreamCreateWithFlags(&sA, cudaStreamNonBlocking);
        cudaStreamCreateWithFlags(&sB, cudaStreamNonBlocking);
        cudaEventCreateWithFlags(&evF, cudaEventDisableTiming);
        cudaEventCreateWithFlags(&evA, cudaEventDisableTiming);
        cudaEventCreateWithFlags(&evB, cudaEventDisableTiming);
    }

    // fork side streams off the main stream
    cudaEventRecord(evF, 0);
    cudaStreamWaitEvent(sA, evF, 0);
    cudaStreamWaitEvent(sB, evF, 0);

    // side stream A: QKV weight transpose + bias pack
    transpose_qkv_kernel<<<dim3(2, 32, 48), dim3(32, 8), 0, sA>>>(Wq, Wk, Wv, p_wt);
    pack_bias_kernel<<<QKV_LD / 256, 256, 0, sA>>>(bq, bk, bv, p_bqkv);
    cudaEventRecord(evA, sA);
    // side stream B: MLP weight transposes
    transpose_kernel_h16<<<dim3(HIDV / 32, DIMV / 32), dim3(32, 8), 0, sB>>>(W1, p_w1t, DIMV, HIDV);
    transpose_kernel_h16<<<dim3(DIMV / 32, HIDV / 32), dim3(32, 8), 0, sB>>>(W2, p_w2t, HIDV, DIMV);
    cudaEventRecord(evB, sB);

    // main stream
    ln_kernel<<<NTOK, 256>>>(x, ln1g, ln1b, p_h);
    cudaStreamWaitEvent(0, evA, 0);
    gemm_f16<0,0,1><<<dim3(QKV_LD / BN, NTOK / BM), 512, GEMM_SMEM_BYTES>>>(
        p_h, p_wt, p_bqkv, nullptr, p_qkv, QKV_LD, DIMV);
    attn_kernel<<<dim3(SEQ / BQ, 64), 256, ATTN_SMEM_B>>>(p_qkv, p_o);
    add_dln_kernel<<<NTOK, 256>>>(x, p_o, ln2g, ln2b, fclg, fclb, p_x2, p_h2);
    cudaStreamWaitEvent(0, evB, 0);
    gemm_f16<1,0,1><<<dim3(HIDV / BN, NTOK / BM), 512, GEMM_SMEM_BYTES>>>(
        p_h2, p_w1t, b1, nullptr, p_mid, HIDV, DIMV);
    gemm_f16<1,1,0><<<dim3(DIMV / BN, NTOK / BM), 512, GEMM_SMEM_BYTES>>>(
        p_mid, p_w2t, b2, p_x2, out, DIMV, HIDV);
}